// round 3
// baseline (speedup 1.0000x reference)
#include <cuda_runtime.h>
#include <math.h>
#include <float.h>

// ---------------- problem constants ----------------
#define B_    32
#define LE_   512      // encoder length
#define LD_   592      // decoder length (label 256 + pred 336)
#define DM_   512      // d_model
#define DFF_  2048
#define NC_   7        // channels
#define NM_   4        // mark features
#define LBL_  256
#define PRED_ 336
#define KT_E  18       // int(3*ln(512))
#define KT_D  19       // int(3*ln(592))

// ---------------- workspace ----------------
#define SZ_XE  ((size_t)B_*LE_*DM_)        // 8388608
#define SZ_XD  ((size_t)B_*LD_*DM_)        // 9699328
#define SZ_H   ((size_t)B_*LD_*DFF_)       // 38797312
#define SZ_G   ((size_t)B_*LD_*LD_)        // 11214848

#define O_XE   ((size_t)0)
#define O_XA   (O_XE + SZ_XE)
#define O_XD   (O_XA + SZ_XD)
#define O_Q    (O_XD + SZ_XD)
#define O_K    (O_Q  + SZ_XD)
#define O_V    (O_K  + SZ_XD)
#define O_T    (O_V  + SZ_XD)
#define O_H    (O_T  + SZ_XD)
#define O_G    (O_H  + SZ_H)
#define O_CORR (O_G  + SZ_G)
#define O_ENC  (O_CORR + (size_t)B_*LD_)
#define O_TS   (O_ENC + SZ_XE)
#define O_SEA  (O_TS + SZ_XD)
#define O_MEAN (O_SEA + (size_t)B_*LE_*NC_)
#define O_WGT  (O_MEAN + (size_t)B_*NC_)
#define WS_TOTAL (O_WGT + (size_t)B_*32)

__device__ __align__(256) float g_ws[WS_TOTAL];
__device__ int g_delay[B_*32];

// ---------------- helpers ----------------
__device__ __forceinline__ float gelu_exact(float v) {
    return 0.5f * v * (1.0f + erff(v * 0.70710678118654752440f));
}

// ---------------- prep: seasonal + mean of x_enc ----------------
__global__ void k_sea(const float* __restrict__ xe, float* __restrict__ sea) {
    int i = blockIdx.x * blockDim.x + threadIdx.x;
    if (i >= B_*LE_*NC_) return;
    int c = i % NC_;
    int t = (i / NC_) % LE_;
    int b = i / (NC_*LE_);
    float s = 0.f;
    #pragma unroll
    for (int j = -12; j <= 12; j++) {
        int tt = t + j; tt = tt < 0 ? 0 : (tt >= LE_ ? LE_-1 : tt);
        s += xe[((size_t)b*LE_ + tt)*NC_ + c];
    }
    sea[i] = xe[i] - s * (1.0f/25.0f);
}

__global__ void k_meanc(const float* __restrict__ xe, float* __restrict__ mb) {
    int i = threadIdx.x;
    if (i >= B_*NC_) return;
    int b = i / NC_, c = i % NC_;
    float s = 0.f;
    for (int t = 0; t < LE_; t++) s += xe[((size_t)b*LE_ + t)*NC_ + c];
    mb[i] = s * (1.0f/LE_);
}

// ---------------- embeds (circular conv width 3 + mark proj) ----------------
__global__ void k_embed_enc(const float* __restrict__ xe, const float* __restrict__ mk_in,
                            const float* __restrict__ Wemb, const float* __restrict__ Wm,
                            float* __restrict__ out) {
    int t = blockIdx.x, b = blockIdx.y, d = threadIdx.x;
    __shared__ float xv[21];
    __shared__ float mk[NM_];
    int tid = threadIdx.x;
    if (tid < 21) {
        int j = tid / NC_, c = tid % NC_;
        int r = (t - 1 + j + LE_) % LE_;
        xv[tid] = xe[((size_t)b*LE_ + r)*NC_ + c];
    } else if (tid < 21 + NM_) {
        int m = tid - 21;
        mk[m] = mk_in[((size_t)b*LE_ + t)*NM_ + m];
    }
    __syncthreads();
    float acc = 0.f;
    #pragma unroll
    for (int jc = 0; jc < 21; jc++) acc += xv[jc] * Wemb[(size_t)jc*DM_ + d];
    #pragma unroll
    for (int m = 0; m < NM_; m++) acc += mk[m] * Wm[(size_t)m*DM_ + d];
    out[((size_t)b*LE_ + t)*DM_ + d] = acc;
}

__global__ void k_embed_dec(const float* __restrict__ sea, const float* __restrict__ mk_enc,
                            const float* __restrict__ mk_dec,
                            const float* __restrict__ Wemb, const float* __restrict__ Wm,
                            float* __restrict__ out) {
    int t = blockIdx.x, b = blockIdx.y, d = threadIdx.x;
    __shared__ float xv[21];
    __shared__ float mk[NM_];
    int tid = threadIdx.x;
    if (tid < 21) {
        int j = tid / NC_, c = tid % NC_;
        int r = (t - 1 + j + LD_) % LD_;
        xv[tid] = (r < LBL_) ? sea[((size_t)b*LE_ + LBL_ + r)*NC_ + c] : 0.f;
    } else if (tid < 21 + NM_) {
        int m = tid - 21;
        mk[m] = (t < LBL_) ? mk_enc[((size_t)b*LE_ + LBL_ + t)*NM_ + m]
                           : mk_dec[((size_t)b*PRED_ + (t - LBL_))*NM_ + m];
    }
    __syncthreads();
    float acc = 0.f;
    #pragma unroll
    for (int jc = 0; jc < 21; jc++) acc += xv[jc] * Wemb[(size_t)jc*DM_ + d];
    #pragma unroll
    for (int m = 0; m < NM_; m++) acc += mk[m] * Wm[(size_t)m*DM_ + d];
    out[((size_t)b*LD_ + t)*DM_ + d] = acc;
}

// ---------------- SGEMM NN: C = act(A(MxK) * W(KxN) + bias) ----------------
// M%128==0, N%128==0, K%8==0 (guaranteed by call sites)
__global__ void __launch_bounds__(256) k_gemm_nn(
    const float* __restrict__ A, const float* __restrict__ W,
    const float* __restrict__ bias, float* __restrict__ C,
    int M, int N, int K, int act)
{
    __shared__ float As[8][128];
    __shared__ float Bs[8][128];
    const int tid = threadIdx.x;
    const int tx = tid & 15, ty = tid >> 4;
    const int bm = blockIdx.y, bn = blockIdx.x;
    const float* Ab = A + (size_t)bm * 128 * K;
    const float* Wb = W + (size_t)bn * 128;
    float acc[8][8];
    #pragma unroll
    for (int i = 0; i < 8; i++)
        #pragma unroll
        for (int j = 0; j < 8; j++) acc[i][j] = 0.f;
    const int aR = tid >> 1, aC = (tid & 1) * 4;
    const int bR = tid >> 5, bC = (tid & 31) * 4;
    for (int k0 = 0; k0 < K; k0 += 8) {
        float4 a4 = *(const float4*)(Ab + (size_t)aR*K + k0 + aC);
        As[aC+0][aR] = a4.x; As[aC+1][aR] = a4.y; As[aC+2][aR] = a4.z; As[aC+3][aR] = a4.w;
        *(float4*)&Bs[bR][bC] = *(const float4*)(Wb + (size_t)(k0 + bR)*N + bC);
        __syncthreads();
        #pragma unroll
        for (int kk = 0; kk < 8; kk++) {
            float4 m0 = *(float4*)&As[kk][ty*8], m1 = *(float4*)&As[kk][ty*8+4];
            float4 n0 = *(float4*)&Bs[kk][tx*8], n1 = *(float4*)&Bs[kk][tx*8+4];
            float rm[8] = {m0.x,m0.y,m0.z,m0.w,m1.x,m1.y,m1.z,m1.w};
            float rn[8] = {n0.x,n0.y,n0.z,n0.w,n1.x,n1.y,n1.z,n1.w};
            #pragma unroll
            for (int i = 0; i < 8; i++)
                #pragma unroll
                for (int j = 0; j < 8; j++) acc[i][j] = fmaf(rm[i], rn[j], acc[i][j]);
        }
        __syncthreads();
    }
    #pragma unroll
    for (int i = 0; i < 8; i++) {
        int r = bm*128 + ty*8 + i;
        #pragma unroll
        for (int j = 0; j < 8; j++) {
            int c = bn*128 + tx*8 + j;
            float v = acc[i][j];
            if (bias) v += bias[c];
            if (act) v = gelu_exact(v);
            C[(size_t)r*N + c] = v;
        }
    }
}

// ---------------- batched Gram NT: G[b] = Q[b] (LxK) * Km[b]^T, Km rows>=S => 0
__global__ void __launch_bounds__(256) k_gemm_nt(
    const float* __restrict__ Q, const float* __restrict__ Km,
    float* __restrict__ G, int L, int S, int K, int qbs, int kbs, int gbs)
{
    int b = blockIdx.z;
    const float* Qb = Q + (size_t)b*qbs;
    const float* Kb = Km + (size_t)b*kbs;
    float* Gb = G + (size_t)b*gbs;
    __shared__ float As[8][128];
    __shared__ float Bs[8][128];
    const int tid = threadIdx.x, tx = tid & 15, ty = tid >> 4;
    const int bm = blockIdx.y, bn = blockIdx.x;
    float acc[8][8];
    #pragma unroll
    for (int i = 0; i < 8; i++)
        #pragma unroll
        for (int j = 0; j < 8; j++) acc[i][j] = 0.f;
    const int lr = tid >> 1, c4 = (tid & 1) * 4;
    const int ar = bm*128 + lr, br = bn*128 + lr;
    for (int k0 = 0; k0 < K; k0 += 8) {
        float4 a4 = make_float4(0.f,0.f,0.f,0.f);
        if (ar < L) a4 = *(const float4*)(Qb + (size_t)ar*K + k0 + c4);
        float4 b4 = make_float4(0.f,0.f,0.f,0.f);
        if (br < S) b4 = *(const float4*)(Kb + (size_t)br*K + k0 + c4);
        As[c4+0][lr] = a4.x; As[c4+1][lr] = a4.y; As[c4+2][lr] = a4.z; As[c4+3][lr] = a4.w;
        Bs[c4+0][lr] = b4.x; Bs[c4+1][lr] = b4.y; Bs[c4+2][lr] = b4.z; Bs[c4+3][lr] = b4.w;
        __syncthreads();
        #pragma unroll
        for (int kk = 0; kk < 8; kk++) {
            float4 m0 = *(float4*)&As[kk][ty*8], m1 = *(float4*)&As[kk][ty*8+4];
            float4 n0 = *(float4*)&Bs[kk][tx*8], n1 = *(float4*)&Bs[kk][tx*8+4];
            float rm[8] = {m0.x,m0.y,m0.z,m0.w,m1.x,m1.y,m1.z,m1.w};
            float rn[8] = {n0.x,n0.y,n0.z,n0.w,n1.x,n1.y,n1.z,n1.w};
            #pragma unroll
            for (int i = 0; i < 8; i++)
                #pragma unroll
                for (int j = 0; j < 8; j++) acc[i][j] = fmaf(rm[i], rn[j], acc[i][j]);
        }
        __syncthreads();
    }
    #pragma unroll
    for (int i = 0; i < 8; i++) {
        int r = bm*128 + ty*8 + i;
        if (r >= L) break;
        #pragma unroll
        for (int j = 0; j < 8; j++) {
            int c = bn*128 + tx*8 + j;
            if (c < L) Gb[(size_t)r*L + c] = acc[i][j];
        }
    }
}

// ---------------- mean_corr[b,tau] = (1/DM) sum_t G[t, (t-tau)%L] ----------------
__global__ void k_corr(const float* __restrict__ G, float* __restrict__ corr, int L, int gbs) {
    int b = blockIdx.y, tau = blockIdx.x, tid = threadIdx.x;
    const float* Gb = G + (size_t)b*gbs;
    float s = 0.f;
    for (int t = tid; t < L; t += 256) {
        int j = t - tau; if (j < 0) j += L;
        s += Gb[(size_t)t*L + j];
    }
    __shared__ float red[256];
    red[tid] = s; __syncthreads();
    for (int st = 128; st > 0; st >>= 1) {
        if (tid < st) red[tid] += red[tid + st];
        __syncthreads();
    }
    if (tid == 0) corr[(size_t)b*L + tau] = red[0] * (1.0f/DM_);
}

// ---------------- exact top-k (lower-index tiebreak) + softmax ----------------
__global__ void k_topk(const float* __restrict__ corr, int L, int KT,
                       int* __restrict__ delay, float* __restrict__ wgt) {
    int b = blockIdx.x, tid = threadIdx.x;
    __shared__ float vals[640];
    __shared__ float rv[256];
    __shared__ int ri[256];
    __shared__ float tv[32];
    __shared__ int tix[32];
    for (int i = tid; i < L; i += 256) vals[i] = corr[(size_t)b*L + i];
    __syncthreads();
    for (int kt = 0; kt < KT; kt++) {
        float bv = -FLT_MAX; int bi = 0x7fffffff;
        for (int i = tid; i < L; i += 256) {
            float v = vals[i];
            if (v > bv || (v == bv && i < bi)) { bv = v; bi = i; }
        }
        rv[tid] = bv; ri[tid] = bi; __syncthreads();
        for (int st = 128; st > 0; st >>= 1) {
            if (tid < st) {
                float v2 = rv[tid+st]; int i2 = ri[tid+st];
                if (v2 > rv[tid] || (v2 == rv[tid] && i2 < ri[tid])) { rv[tid] = v2; ri[tid] = i2; }
            }
            __syncthreads();
        }
        if (tid == 0) { tv[kt] = rv[0]; tix[kt] = ri[0]; vals[ri[0]] = -FLT_MAX; }
        __syncthreads();
    }
    if (tid == 0) {
        float mx = tv[0], s = 0.f;
        float e[32];
        for (int i = 0; i < KT; i++) { e[i] = expf(tv[i] - mx); s += e[i]; }
        float inv = 1.0f / s;
        for (int i = 0; i < KT; i++) {
            wgt[b*32 + i] = e[i] * inv;
            delay[b*32 + i] = tix[i];
        }
    }
}

// ---------------- weighted circular gather ----------------
__global__ void k_agg(const float* __restrict__ V, const int* __restrict__ delay,
                      const float* __restrict__ wgt, float* __restrict__ O,
                      int L, int S, int KT, int vbs) {
    int t = blockIdx.x, b = blockIdx.y, d = threadIdx.x;
    __shared__ int sd[32];
    __shared__ float sw[32];
    if (d < KT) { sd[d] = delay[b*32 + d]; sw[d] = wgt[b*32 + d]; }
    __syncthreads();
    float acc = 0.f;
    for (int i = 0; i < KT; i++) {
        int r = t + sd[i]; if (r >= L) r -= L;
        if (r < S) acc += sw[i] * V[(size_t)b*vbs + (size_t)r*DM_ + d];
    }
    O[((size_t)b*L + t)*DM_ + d] = acc;
}

// ---------------- fused residual add + series_decomp (movavg k=25, edge pad) ----
// tmode: 0 = no trend out, 1 = write trend, 2 = accumulate trend
__global__ void k_add_decomp(const float* __restrict__ X, const float* __restrict__ A,
                             float* __restrict__ S, float* __restrict__ T,
                             int L, int tmode) {
    int b = blockIdx.y, ch = blockIdx.x, d = threadIdx.x;
    int CH = (L + 7) / 8;
    int t0 = ch * CH, t1 = min(t0 + CH, L);
    if (t0 >= L) return;
    const size_t base = (size_t)b * L * DM_ + d;
    float w = 0.f;
    for (int j = -12; j <= 12; j++) {
        int tt = t0 + j; tt = tt < 0 ? 0 : (tt >= L ? L-1 : tt);
        size_t idx = base + (size_t)tt * DM_;
        w += X[idx] + A[idx];
    }
    for (int t = t0; t < t1; t++) {
        size_t idx = base + (size_t)t * DM_;
        float cur = X[idx] + A[idx];
        float m = w * (1.0f/25.0f);
        S[idx] = cur - m;
        if (tmode == 1) T[idx] = m;
        else if (tmode == 2) T[idx] += m;
        int ta = t + 13; ta = ta >= L ? L-1 : ta;
        int tr = t - 12; tr = tr < 0 ? 0 : tr;
        size_t ia = base + (size_t)ta * DM_;
        size_t ir = base + (size_t)tr * DM_;
        w += (X[ia] + A[ia]) - (X[ir] + A[ir]);
    }
}

// ---------------- layernorm over last dim ----------------
__global__ void k_ln(const float* __restrict__ X, const float* __restrict__ g,
                     const float* __restrict__ be, float* __restrict__ Y) {
    int row = blockIdx.x, tid = threadIdx.x;
    __shared__ float buf[DM_];
    __shared__ float red[256];
    __shared__ float smu, sinv;
    const float* xr = X + (size_t)row * DM_;
    float s = 0.f;
    for (int i = tid; i < DM_; i += 256) { float v = xr[i]; buf[i] = v; s += v; }
    red[tid] = s; __syncthreads();
    for (int st = 128; st > 0; st >>= 1) { if (tid < st) red[tid] += red[tid+st]; __syncthreads(); }
    if (tid == 0) smu = red[0] * (1.0f/DM_);
    __syncthreads();
    float mu = smu, s2 = 0.f;
    for (int i = tid; i < DM_; i += 256) { float dv = buf[i] - mu; s2 += dv*dv; }
    red[tid] = s2; __syncthreads();
    for (int st = 128; st > 0; st >>= 1) { if (tid < st) red[tid] += red[tid+st]; __syncthreads(); }
    if (tid == 0) sinv = rsqrtf(red[0] * (1.0f/DM_) + 1e-5f);
    __syncthreads();
    float inv = sinv;
    for (int i = tid; i < DM_; i += 256)
        Y[(size_t)row*DM_ + i] = (buf[i] - mu) * inv * g[i] + be[i];
}

// ---------------- subtract per-(b,d) time mean, in place ----------------
__global__ void k_submean(float* __restrict__ Y, int L) {
    int b = blockIdx.x, d = threadIdx.x;
    size_t base = (size_t)b * L * DM_ + d;
    float s = 0.f;
    for (int t = 0; t < L; t++) s += Y[base + (size_t)t*DM_];
    s *= (1.0f / L);
    for (int t = 0; t < L; t++) Y[base + (size_t)t*DM_] -= s;
}

// ---------------- final: trend_init(mean) + circconv3(tsum,W_trend) + proj ----
__global__ void k_final(const float* __restrict__ XLN, const float* __restrict__ TS,
                        const float* __restrict__ meanb, const float* __restrict__ Wt,
                        const float* __restrict__ Wp, const float* __restrict__ bp,
                        float* __restrict__ out) {
    int p = blockIdx.x, b = blockIdx.y, tid = threadIdx.x;
    int t = LBL_ + p;
    int r0 = (t - 1 + LD_) % LD_;
    int r2 = (t + 1) % LD_;
    float acc[NC_];
    #pragma unroll
    for (int c = 0; c < NC_; c++) acc[c] = 0.f;
    for (int d = tid; d < DM_; d += 256) {
        float xv  = XLN[((size_t)b*LD_ + t )*DM_ + d];
        float tv0 = TS [((size_t)b*LD_ + r0)*DM_ + d];
        float tv1 = TS [((size_t)b*LD_ + t )*DM_ + d];
        float tv2 = TS [((size_t)b*LD_ + r2)*DM_ + d];
        #pragma unroll
        for (int c = 0; c < NC_; c++) {
            acc[c] += xv  * Wp[(size_t)d*NC_ + c]
                    + tv0 * Wt[((size_t)0*DM_ + d)*NC_ + c]
                    + tv1 * Wt[((size_t)1*DM_ + d)*NC_ + c]
                    + tv2 * Wt[((size_t)2*DM_ + d)*NC_ + c];
        }
    }
    __shared__ float red[256];
    for (int c = 0; c < NC_; c++) {
        red[tid] = acc[c]; __syncthreads();
        for (int st = 128; st > 0; st >>= 1) { if (tid < st) red[tid] += red[tid+st]; __syncthreads(); }
        if (tid == 0)
            out[((size_t)b*PRED_ + p)*NC_ + c] = red[0] + meanb[b*NC_ + c] + bp[c];
        __syncthreads();
    }
}

// ================= host orchestration =================
static inline void gemm_nn(const float* A, const float* W, const float* bias,
                           float* C, int M, int N, int K, int act) {
    dim3 grid(N/128, M/128);
    k_gemm_nn<<<grid, 256>>>(A, W, bias, C, M, N, K, act);
}

extern "C" void kernel_launch(void* const* d_in, const int* in_sizes, int n_in,
                              void* d_out, int out_size) {
    const float* x_enc      = (const float*)d_in[0];
    const float* x_mark_enc = (const float*)d_in[1];
    const float* x_mark_dec = (const float*)d_in[3];
    const float* W_enc_emb  = (const float*)d_in[4];
    const float* W_mark_enc = (const float*)d_in[5];
    const float* W_dec_emb  = (const float*)d_in[6];
    const float* W_mark_dec = (const float*)d_in[7];
    const float* eW_attn    = (const float*)d_in[8];
    const float* eb_attn    = (const float*)d_in[9];
    const float* eW1        = (const float*)d_in[10];
    const float* eW2        = (const float*)d_in[11];
    const float* eg         = (const float*)d_in[12];
    const float* ebeta      = (const float*)d_in[13];
    const float* sW         = (const float*)d_in[14];
    const float* sb         = (const float*)d_in[15];
    const float* cW         = (const float*)d_in[16];
    const float* cb         = (const float*)d_in[17];
    const float* dW1        = (const float*)d_in[18];
    const float* dW2        = (const float*)d_in[19];
    const float* W_trend    = (const float*)d_in[20];
    const float* dg         = (const float*)d_in[21];
    const float* dbeta      = (const float*)d_in[22];
    const float* Wproj      = (const float*)d_in[23];
    const float* bproj      = (const float*)d_in[24];
    float* out = (float*)d_out;

    float* ws = nullptr;
    cudaGetSymbolAddress((void**)&ws, g_ws);
    int* dly = nullptr;
    cudaGetSymbolAddress((void**)&dly, g_delay);

    float* XE   = ws + O_XE;
    float* XA   = ws + O_XA;
    float* XD   = ws + O_XD;
    float* Qb   = ws + O_Q;
    float* Kb   = ws + O_K;
    float* Vb   = ws + O_V;
    float* Tb   = ws + O_T;
    float* Hb   = ws + O_H;
    float* Gb   = ws + O_G;
    float* CORR = ws + O_CORR;
    float* ENC  = ws + O_ENC;
    float* TS   = ws + O_TS;
    float* SEA  = ws + O_SEA;
    float* MEANB= ws + O_MEAN;
    float* WGT  = ws + O_WGT;

    // ---- prep ----
    k_sea<<<(B_*LE_*NC_ + 255)/256, 256>>>(x_enc, SEA);
    k_meanc<<<1, 256>>>(x_enc, MEANB);
    k_embed_enc<<<dim3(LE_, B_), DM_>>>(x_enc, x_mark_enc, W_enc_emb, W_mark_enc, XE);

    // ---- encoder: 2 layers ----
    float* x = XE;
    for (int l = 0; l < 2; l++) {
        const float* W  = eW_attn + (size_t)l*4*DM_*DM_;
        const float* bb = eb_attn + (size_t)l*4*DM_;
        gemm_nn(x, W + 0*(size_t)DM_*DM_, bb + 0*DM_, Qb, B_*LE_, DM_, DM_, 0);
        gemm_nn(x, W + 1*(size_t)DM_*DM_, bb + 1*DM_, Kb, B_*LE_, DM_, DM_, 0);
        gemm_nn(x, W + 2*(size_t)DM_*DM_, bb + 2*DM_, Vb, B_*LE_, DM_, DM_, 0);
        k_gemm_nt<<<dim3(4,4,B_), 256>>>(Qb, Kb, Gb, LE_, LE_, DM_, LE_*DM_, LE_*DM_, LE_*LE_);
        k_corr<<<dim3(LE_, B_), 256>>>(Gb, CORR, LE_, LE_*LE_);
        k_topk<<<B_, 256>>>(CORR, LE_, KT_E, dly, WGT);
        k_agg<<<dim3(LE_, B_), DM_>>>(Vb, dly, WGT, Qb, LE_, LE_, KT_E, LE_*DM_);
        gemm_nn(Qb, W + 3*(size_t)DM_*DM_, bb + 3*DM_, Tb, B_*LE_, DM_, DM_, 0);
        float* nx = (x == XE) ? XA : XE;
        k_add_decomp<<<dim3(8, B_), DM_>>>(x, Tb, nx, nullptr, LE_, 0);
        x = nx;
        gemm_nn(x,  eW1 + (size_t)l*DM_*DFF_, nullptr, Hb, B_*LE_, DFF_, DM_, 1);
        gemm_nn(Hb, eW2 + (size_t)l*DFF_*DM_, nullptr, Tb, B_*LE_, DM_, DFF_, 0);
        nx = (x == XE) ? XA : XE;
        k_add_decomp<<<dim3(8, B_), DM_>>>(x, Tb, nx, nullptr, LE_, 0);
        x = nx;
    }
    // enc_out = my_layernorm(x)
    k_ln<<<B_*LE_, 256>>>(x, eg, ebeta, ENC);
    k_submean<<<B_, DM_>>>(ENC, LE_);

    // ---- decoder ----
    k_embed_dec<<<dim3(LD_, B_), DM_>>>(SEA, x_mark_enc, x_mark_dec, W_dec_emb, W_mark_dec, XD);
    x = XD;

    // self attention
    gemm_nn(x, sW + 0*(size_t)DM_*DM_, sb + 0*DM_, Qb, B_*LD_, DM_, DM_, 0);
    gemm_nn(x, sW + 1*(size_t)DM_*DM_, sb + 1*DM_, Kb, B_*LD_, DM_, DM_, 0);
    gemm_nn(x, sW + 2*(size_t)DM_*DM_, sb + 2*DM_, Vb, B_*LD_, DM_, DM_, 0);
    k_gemm_nt<<<dim3(5,5,B_), 256>>>(Qb, Kb, Gb, LD_, LD_, DM_, LD_*DM_, LD_*DM_, LD_*LD_);
    k_corr<<<dim3(LD_, B_), 256>>>(Gb, CORR, LD_, LD_*LD_);
    k_topk<<<B_, 256>>>(CORR, LD_, KT_D, dly, WGT);
    k_agg<<<dim3(LD_, B_), DM_>>>(Vb, dly, WGT, Qb, LD_, LD_, KT_D, LD_*DM_);
    gemm_nn(Qb, sW + 3*(size_t)DM_*DM_, sb + 3*DM_, Tb, B_*LD_, DM_, DM_, 0);
    k_add_decomp<<<dim3(8, B_), DM_>>>(x, Tb, XA, TS, LD_, 1);
    x = XA;

    // cross attention (S = 512, K/V from enc_out, zero-padded via S mask)
    gemm_nn(x,   cW + 0*(size_t)DM_*DM_, cb + 0*DM_, Qb, B_*LD_, DM_, DM_, 0);
    gemm_nn(ENC, cW + 1*(size_t)DM_*DM_, cb + 1*DM_, Kb, B_*LE_, DM_, DM_, 0);
    gemm_nn(ENC, cW + 2*(size_t)DM_*DM_, cb + 2*DM_, Vb, B_*LE_, DM_, DM_, 0);
    k_gemm_nt<<<dim3(5,5,B_), 256>>>(Qb, Kb, Gb, LD_, LE_, DM_, LD_*DM_, LE_*DM_, LD_*LD_);
    k_corr<<<dim3(LD_, B_), 256>>>(Gb, CORR, LD_, LD_*LD_);
    k_topk<<<B_, 256>>>(CORR, LD_, KT_D, dly, WGT);
    k_agg<<<dim3(LD_, B_), DM_>>>(Vb, dly, WGT, Qb, LD_, LE_, KT_D, LE_*DM_);
    gemm_nn(Qb, cW + 3*(size_t)DM_*DM_, cb + 3*DM_, Tb, B_*LD_, DM_, DM_, 0);
    k_add_decomp<<<dim3(8, B_), DM_>>>(x, Tb, XD, TS, LD_, 2);
    x = XD;

    // FFN
    gemm_nn(x,  dW1, nullptr, Hb, B_*LD_, DFF_, DM_, 1);
    gemm_nn(Hb, dW2, nullptr, Tb, B_*LD_, DM_, DFF_, 0);
    k_add_decomp<<<dim3(8, B_), DM_>>>(x, Tb, XA, TS, LD_, 2);
    x = XA;

    // final layernorm + output assembly
    k_ln<<<B_*LD_, 256>>>(x, dg, dbeta, Qb);
    k_submean<<<B_, DM_>>>(Qb, LD_);
    k_final<<<dim3(PRED_, B_), 256>>>(Qb, TS, MEANB, W_trend, Wproj, bproj, out);
}

// round 6
// speedup vs baseline: 2.1561x; 2.1561x over previous
#include <cuda_runtime.h>
#include <cuda_bf16.h>
#include <math.h>
#include <float.h>
#include <stdint.h>

typedef __nv_bfloat16 bf;

// ---------------- problem constants ----------------
#define B_    32
#define LE_   512      // encoder length
#define LD_   592      // decoder length (label 256 + pred 336)
#define LP_   640      // padded decoder length (multiple of 128)
#define DM_   512      // d_model
#define DFF_  2048
#define NC_   7        // channels
#define NM_   4        // mark features
#define LBL_  256
#define PRED_ 336
#define KT_E  18       // int(3*ln(512))
#define KT_D  19       // int(3*ln(592))

// ---------------- fp32 workspace ----------------
#define SZ_XE  ((size_t)B_*LE_*DM_)
#define SZ_XD  ((size_t)B_*LD_*DM_)
#define SZ_G   ((size_t)B_*LD_*LD_)

#define O_XE   ((size_t)0)
#define O_XA   (O_XE + SZ_XE)
#define O_XD   (O_XA + SZ_XD)
#define O_Q    (O_XD + SZ_XD)
#define O_K    (O_Q  + SZ_XD)
#define O_V    (O_K  + SZ_XD)
#define O_T    (O_V  + SZ_XD)
#define O_G    (O_T  + SZ_XD)
#define O_CORR (O_G  + SZ_G)
#define O_ENC  (O_CORR + (size_t)B_*LD_)
#define O_TS   (O_ENC + SZ_XE)
#define O_SEA  (O_TS + SZ_XD)
#define O_MEAN (O_SEA + (size_t)B_*LE_*NC_)
#define O_WGT  (O_MEAN + (size_t)B_*NC_)
#define WS_TOTAL (O_WGT + (size_t)B_*32)

__device__ __align__(256) float g_ws[WS_TOTAL];
__device__ int g_delay[B_*32];

// ---------------- bf16 split workspace ----------------
#define SZ_AB  ((size_t)B_*LP_*DM_)           // x / agg / enc split
#define SZ_QB  ((size_t)B_*LP_*DM_)           // Gram A (padded)
#define SZ_KB  ((size_t)B_*LP_*DM_)           // Gram B (padded)
#define SZ_HB  ((size_t)B_*LD_*DFF_)          // FFN hidden split
// weight slots (transposed, [N][K])
#define OW_EATT ((size_t)0)
#define OW_EW1  ((size_t)2097152)
#define OW_EW2  ((size_t)4194304)
#define OW_SW   ((size_t)6291456)
#define OW_CW   ((size_t)7340032)
#define OW_DW1  ((size_t)8388608)
#define OW_DW2  ((size_t)9437184)
#define SZ_WB   ((size_t)10485760)

__device__ __align__(256) bf g_abh[SZ_AB];
__device__ __align__(256) bf g_abl[SZ_AB];
__device__ __align__(256) bf g_qbh[SZ_QB];
__device__ __align__(256) bf g_qbl[SZ_QB];
__device__ __align__(256) bf g_kbh[SZ_KB];
__device__ __align__(256) bf g_kbl[SZ_KB];
__device__ __align__(256) bf g_hbh[SZ_HB];
__device__ __align__(256) bf g_hbl[SZ_HB];
__device__ __align__(256) bf g_wbh[SZ_WB];
__device__ __align__(256) bf g_wbl[SZ_WB];

// ---------------- helpers ----------------
__device__ __forceinline__ float gelu_exact(float v) {
    return 0.5f * v * (1.0f + erff(v * 0.70710678118654752440f));
}
__device__ __forceinline__ uint32_t s2u(const void* p){
    uint32_t a;
    asm("{ .reg .u64 t; cvta.to.shared.u64 t, %1; cvt.u32.u64 %0, t; }":"=r"(a):"l"(p));
    return a;
}
#define SWZ(o) ((o) ^ (((o)>>3)&0x70))

#define LDSM4(r, ad) \
    asm volatile("ldmatrix.sync.aligned.m8n8.x4.shared.b16 {%0,%1,%2,%3}, [%4];" \
        : "=r"((r)[0]), "=r"((r)[1]), "=r"((r)[2]), "=r"((r)[3]) : "r"(ad))

#define MMA16816(d, a, b0, b1) \
    asm volatile("mma.sync.aligned.m16n8k16.row.col.f32.bf16.bf16.f32 " \
        "{%0,%1,%2,%3}, {%4,%5,%6,%7}, {%8,%9}, {%0,%1,%2,%3};" \
        : "+f"((d)[0]), "+f"((d)[1]), "+f"((d)[2]), "+f"((d)[3]) \
        : "r"((a)[0]), "r"((a)[1]), "r"((a)[2]), "r"((a)[3]), "r"(b0), "r"(b1))

// ---------------- conversion kernels ----------------
__global__ void k_cvt(const float* __restrict__ X, bf* __restrict__ H,
                      bf* __restrict__ Lo, int n){
    int i = blockIdx.x*256 + threadIdx.x;
    if (i >= n) return;
    float x = X[i];
    bf h = __float2bfloat16(x);
    H[i] = h; Lo[i] = __float2bfloat16(x - __bfloat162float(h));
}

// pad rows >= Lv with zero; src [B][Lv][DM], dst [B][Lp][DM]
__global__ void k_cvt_pad(const float* __restrict__ X, bf* __restrict__ H,
                          bf* __restrict__ Lo, int Lv, int Lp){
    int i = blockIdx.x*256 + threadIdx.x;
    int total = B_*Lp*DM_;
    if (i >= total) return;
    int col = i & (DM_-1);
    int row = (i/DM_) % Lp;
    int b = i/(DM_*Lp);
    float x = 0.f;
    if (row < Lv) x = X[((size_t)b*Lv + row)*DM_ + col];
    bf h = __float2bfloat16(x);
    H[i] = h; Lo[i] = __float2bfloat16(x - __bfloat162float(h));
}

// transpose + split: W[K][N] -> TH/TL [N][K]
__global__ void k_cvtT(const float* __restrict__ W, bf* __restrict__ TH,
                       bf* __restrict__ TL, int K, int N){
    __shared__ float t[32][33];
    int n0 = blockIdx.x*32, k0 = blockIdx.y*32;
    int tx = threadIdx.x, ty = threadIdx.y;
    #pragma unroll
    for (int i = 0; i < 32; i += 8)
        t[ty+i][tx] = W[(size_t)(k0+ty+i)*N + n0 + tx];
    __syncthreads();
    #pragma unroll
    for (int i = 0; i < 32; i += 8) {
        float x = t[tx][ty+i];
        bf h = __float2bfloat16(x);
        size_t o = (size_t)(n0+ty+i)*K + k0 + tx;
        TH[o] = h; TL[o] = __float2bfloat16(x - __bfloat162float(h));
    }
}

// ---------------- bf16x3 mma.sync GEMM ----------------
// D[m][n] = sum_k (Ah+Al)[m][k]*(Bh+Bl)[n][k] (AlBl dropped), fp32 accum.
// CTA tile 128x128, K chunks of 64, double-buffered cp.async, NT via ldmatrix.
#define SMEM_SZ 65536

__device__ __forceinline__ void ldchunk(uint32_t sA, uint32_t sB,
    const bf* __restrict__ Aq, const bf* __restrict__ Bq,
    int K, int k0, int tid)
{
    #pragma unroll
    for (int i = 0; i < 8; i++) {
        int idx = i*256 + tid;
        int op  = idx >> 10;
        int row = (idx >> 3) & 127;
        int c16 = idx & 7;
        uint32_t dst = (op ? sB : sA) + SWZ(row*128 + c16*16);
        const bf* src = (op ? Bq : Aq) + (size_t)row*K + k0 + c16*8;
        asm volatile("cp.async.cg.shared.global [%0], [%1], 16;\n"::"r"(dst),"l"(src));
    }
    asm volatile("cp.async.commit_group;\n":::"memory");
}

__global__ void __launch_bounds__(256,2) k_mma(
    const bf* __restrict__ Ah, const bf* __restrict__ Al,
    const bf* __restrict__ Bh, const bf* __restrict__ Bl,
    float* __restrict__ C, bf* __restrict__ SH, bf* __restrict__ SL,
    int K, int ldc, int rowsV, int colsV,
    long long aB, long long bB, long long cB,
    const float* __restrict__ bias, int act)
{
    extern __shared__ char smem[];
    uint32_t sb0 = s2u(smem);
    const int tid = threadIdx.x, lane = tid & 31, wid = tid >> 5;
    const int bn = blockIdx.x, bm = blockIdx.y, bz = blockIdx.z;
    const bf* Ah2 = Ah + (size_t)bz*aB + (size_t)bm*128*K;
    const bf* Al2 = Al + (size_t)bz*aB + (size_t)bm*128*K;
    const bf* Bh2 = Bh + (size_t)bz*bB + (size_t)bn*128*K;
    const bf* Bl2 = Bl + (size_t)bz*bB + (size_t)bn*128*K;
    const bf* AP[3] = {Ah2, Ah2, Al2};
    const bf* BP[3] = {Bh2, Bl2, Bh2};
    if (C)  C  += (size_t)bz*cB;
    if (SH) { SH += (size_t)bz*cB; SL += (size_t)bz*cB; }

    float acc[4][4][4];
    #pragma unroll
    for (int i = 0; i < 4; i++)
        #pragma unroll
        for (int j = 0; j < 4; j++)
            #pragma unroll
            for (int q = 0; q < 4; q++) acc[i][j][q] = 0.f;

    uint32_t sA[2] = {sb0,          sb0 + 32768u};
    uint32_t sB[2] = {sb0 + 16384u, sb0 + 49152u};
    const int KC = K >> 6, NCH = 3*KC;
    const int m0 = (wid & 1) << 6, n0 = (wid >> 1) << 5;

    ldchunk(sA[0], sB[0], AP[0], BP[0], K, 0, tid);

    for (int c = 0; c < NCH; c++) {
        int s = c & 1;
        if (c+1 < NCH) {
            int sp = (c+1)/KC, kc = (c+1)%KC;
            ldchunk(sA[s^1], sB[s^1], AP[sp], BP[sp], K, kc*64, tid);
            asm volatile("cp.async.wait_group 1;\n":::"memory");
        } else {
            asm volatile("cp.async.wait_group 0;\n":::"memory");
        }
        __syncthreads();

        uint32_t aS = sA[s], bS = sB[s];
        #pragma unroll
        for (int kk = 0; kk < 4; kk++) {
            uint32_t af[4][4];
            #pragma unroll
            for (int mt = 0; mt < 4; mt++) {
                int m = m0 + mt*16 + (lane & 15);
                int kb = kk*32 + ((lane >> 4) << 4);
                uint32_t ad = aS + SWZ(m*128 + kb);
                LDSM4(af[mt], ad);
            }
            uint32_t bf4[2][4];
            #pragma unroll
            for (int nt2 = 0; nt2 < 2; nt2++) {
                int g = lane >> 3;
                int n = n0 + nt2*16 + ((g >> 1) << 3) + (lane & 7);
                int kb = kk*32 + ((g & 1) << 4);
                uint32_t bd = bS + SWZ(n*128 + kb);
                LDSM4(bf4[nt2], bd);
            }
            #pragma unroll
            for (int mt = 0; mt < 4; mt++)
                #pragma unroll
                for (int nt = 0; nt < 4; nt++)
                    MMA16816(acc[mt][nt], af[mt],
                             bf4[nt>>1][(nt&1)*2], bf4[nt>>1][(nt&1)*2+1]);
        }
        __syncthreads();
    }

    // epilogue
    const int gid = lane >> 2, tig = lane & 3;
    #pragma unroll
    for (int mt = 0; mt < 4; mt++) {
        #pragma unroll
        for (int h = 0; h < 2; h++) {
            int row = bm*128 + m0 + mt*16 + gid + h*8;
            if (row >= rowsV) continue;
            #pragma unroll
            for (int nt = 0; nt < 4; nt++) {
                int col = bn*128 + n0 + nt*8 + tig*2;
                if (col >= colsV) continue;
                float v0 = acc[mt][nt][h*2+0];
                float v1 = acc[mt][nt][h*2+1];
                if (bias) { v0 += bias[col]; v1 += bias[col+1]; }
                if (act)  { v0 = gelu_exact(v0); v1 = gelu_exact(v1); }
                size_t o = (size_t)row*ldc + col;
                if (C) *(float2*)(C + o) = make_float2(v0, v1);
                if (SH) {
                    bf h0 = __float2bfloat16(v0), h1 = __float2bfloat16(v1);
                    bf l0 = __float2bfloat16(v0 - __bfloat162float(h0));
                    bf l1 = __float2bfloat16(v1 - __bfloat162float(h1));
                    *(__nv_bfloat162*)(SH + o) = __nv_bfloat162(h0, h1);
                    *(__nv_bfloat162*)(SL + o) = __nv_bfloat162(l0, l1);
                }
            }
        }
    }
}

// ---------------- prep: seasonal + mean of x_enc ----------------
__global__ void k_sea(const float* __restrict__ xe, float* __restrict__ sea) {
    int i = blockIdx.x * blockDim.x + threadIdx.x;
    if (i >= B_*LE_*NC_) return;
    int c = i % NC_;
    int t = (i / NC_) % LE_;
    int b = i / (NC_*LE_);
    float s = 0.f;
    #pragma unroll
    for (int j = -12; j <= 12; j++) {
        int tt = t + j; tt = tt < 0 ? 0 : (tt >= LE_ ? LE_-1 : tt);
        s += xe[((size_t)b*LE_ + tt)*NC_ + c];
    }
    sea[i] = xe[i] - s * (1.0f/25.0f);
}

__global__ void k_meanc(const float* __restrict__ xe, float* __restrict__ mb) {
    int i = threadIdx.x;
    if (i >= B_*NC_) return;
    int b = i / NC_, c = i % NC_;
    float s = 0.f;
    for (int t = 0; t < LE_; t++) s += xe[((size_t)b*LE_ + t)*NC_ + c];
    mb[i] = s * (1.0f/LE_);
}

// ---------------- embeds ----------------
__global__ void k_embed_enc(const float* __restrict__ xe, const float* __restrict__ mk_in,
                            const float* __restrict__ Wemb, const float* __restrict__ Wm,
                            float* __restrict__ out) {
    int t = blockIdx.x, b = blockIdx.y, d = threadIdx.x;
    __shared__ float xv[21];
    __shared__ float mk[NM_];
    int tid = threadIdx.x;
    if (tid < 21) {
        int j = tid / NC_, c = tid % NC_;
        int r = (t - 1 + j + LE_) % LE_;
        xv[tid] = xe[((size_t)b*LE_ + r)*NC_ + c];
    } else if (tid < 21 + NM_) {
        int m = tid - 21;
        mk[m] = mk_in[((size_t)b*LE_ + t)*NM_ + m];
    }
    __syncthreads();
    float acc = 0.f;
    #pragma unroll
    for (int jc = 0; jc < 21; jc++) acc += xv[jc] * Wemb[(size_t)jc*DM_ + d];
    #pragma unroll
    for (int m = 0; m < NM_; m++) acc += mk[m] * Wm[(size_t)m*DM_ + d];
    out[((size_t)b*LE_ + t)*DM_ + d] = acc;
}

__global__ void k_embed_dec(const float* __restrict__ sea, const float* __restrict__ mk_enc,
                            const float* __restrict__ mk_dec,
                            const float* __restrict__ Wemb, const float* __restrict__ Wm,
                            float* __restrict__ out) {
    int t = blockIdx.x, b = blockIdx.y, d = threadIdx.x;
    __shared__ float xv[21];
    __shared__ float mk[NM_];
    int tid = threadIdx.x;
    if (tid < 21) {
        int j = tid / NC_, c = tid % NC_;
        int r = (t - 1 + j + LD_) % LD_;
        xv[tid] = (r < LBL_) ? sea[((size_t)b*LE_ + LBL_ + r)*NC_ + c] : 0.f;
    } else if (tid < 21 + NM_) {
        int m = tid - 21;
        mk[m] = (t < LBL_) ? mk_enc[((size_t)b*LE_ + LBL_ + t)*NM_ + m]
                           : mk_dec[((size_t)b*PRED_ + (t - LBL_))*NM_ + m];
    }
    __syncthreads();
    float acc = 0.f;
    #pragma unroll
    for (int jc = 0; jc < 21; jc++) acc += xv[jc] * Wemb[(size_t)jc*DM_ + d];
    #pragma unroll
    for (int m = 0; m < NM_; m++) acc += mk[m] * Wm[(size_t)m*DM_ + d];
    out[((size_t)b*LD_ + t)*DM_ + d] = acc;
}

// ---------------- mean_corr ----------------
__global__ void k_corr(const float* __restrict__ G, float* __restrict__ corr, int L, int gbs) {
    int b = blockIdx.y, tau = blockIdx.x, tid = threadIdx.x;
    const float* Gb = G + (size_t)b*gbs;
    float s = 0.f;
    for (int t = tid; t < L; t += 256) {
        int j = t - tau; if (j < 0) j += L;
        s += Gb[(size_t)t*L + j];
    }
    __shared__ float red[256];
    red[tid] = s; __syncthreads();
    for (int st = 128; st > 0; st >>= 1) {
        if (tid < st) red[tid] += red[tid + st];
        __syncthreads();
    }
    if (tid == 0) corr[(size_t)b*L + tau] = red[0] * (1.0f/DM_);
}

// ---------------- exact top-k + softmax ----------------
__global__ void k_topk(const float* __restrict__ corr, int L, int KT,
                       int* __restrict__ delay, float* __restrict__ wgt) {
    int b = blockIdx.x, tid = threadIdx.x;
    __shared__ float vals[640];
    __shared__ float rv[256];
    __shared__ int ri[256];
    __shared__ float tv[32];
    __shared__ int tix[32];
    for (int i = tid; i < L; i += 256) vals[i] = corr[(size_t)b*L + i];
    __syncthreads();
    for (int kt = 0; kt < KT; kt++) {
        float bv = -FLT_MAX; int bi = 0x7fffffff;
        for (int i = tid; i < L; i += 256) {
            float v = vals[i];
            if (v > bv || (v == bv && i < bi)) { bv = v; bi = i; }
        }
        rv[tid] = bv; ri[tid] = bi; __syncthreads();
        for (int st = 128; st > 0; st >>= 1) {
            if (tid < st) {
                float v2 = rv[tid+st]; int i2 = ri[tid+st];
                if (v2 > rv[tid] || (v2 == rv[tid] && i2 < ri[tid])) { rv[tid] = v2; ri[tid] = i2; }
            }
            __syncthreads();
        }
        if (tid == 0) { tv[kt] = rv[0]; tix[kt] = ri[0]; vals[ri[0]] = -FLT_MAX; }
        __syncthreads();
    }
    if (tid == 0) {
        float mx = tv[0], s = 0.f;
        float e[32];
        for (int i = 0; i < KT; i++) { e[i] = expf(tv[i] - mx); s += e[i]; }
        float inv = 1.0f / s;
        for (int i = 0; i < KT; i++) {
            wgt[b*32 + i] = e[i] * inv;
            delay[b*32 + i] = tix[i];
        }
    }
}

// ---------------- weighted circular gather (writes split bf16) ----------------
__global__ void k_agg(const float* __restrict__ V, const int* __restrict__ delay,
                      const float* __restrict__ wgt, bf* __restrict__ OH,
                      bf* __restrict__ OL, int L, int S, int KT, int vbs) {
    int t = blockIdx.x, b = blockIdx.y, d = threadIdx.x;
    __shared__ int sd[32];
    __shared__ float sw[32];
    if (d < KT) { sd[d] = delay[b*32 + d]; sw[d] = wgt[b*32 + d]; }
    __syncthreads();
    float acc = 0.f;
    for (int i = 0; i < KT; i++) {
        int r = t + sd[i]; if (r >= L) r -= L;
        if (r < S) acc += sw[i] * V[(size_t)b*vbs + (size_t)r*DM_ + d];
    }
    size_t o = ((size_t)b*L + t)*DM_ + d;
    bf h = __float2bfloat16(acc);
    OH[o] = h; OL[o] = __float2bfloat16(acc - __bfloat162float(h));
}

// ---------------- fused residual add + series_decomp (+ split output) --------
__global__ void k_add_decomp(const float* __restrict__ X, const float* __restrict__ A,
                             float* __restrict__ S, float* __restrict__ T,
                             bf* __restrict__ SH, bf* __restrict__ SL,
                             int L, int tmode) {
    int b = blockIdx.y, ch = blockIdx.x, d = threadIdx.x;
    int CH = (L + 7) / 8;
    int t0 = ch * CH, t1 = min(t0 + CH, L);
    if (t0 >= L) return;
    const size_t base = (size_t)b * L * DM_ + d;
    float w = 0.f;
    for (int j = -12; j <= 12; j++) {
        int tt = t0 + j; tt = tt < 0 ? 0 : (tt >= L ? L-1 : tt);
        size_t idx = base + (size_t)tt * DM_;
        w += X[idx] + A[idx];
    }
    for (int t = t0; t < t1; t++) {
        size_t idx = base + (size_t)t * DM_;
        float cur = X[idx] + A[idx];
        float m = w * (1.0f/25.0f);
        float sv = cur - m;
        S[idx] = sv;
        bf h = __float2bfloat16(sv);
        SH[idx] = h; SL[idx] = __float2bfloat16(sv - __bfloat162float(h));
        if (tmode == 1) T[idx] = m;
        else if (tmode == 2) T[idx] += m;
        int ta = t + 13; ta = ta >= L ? L-1 : ta;
        int tr = t - 12; tr = tr < 0 ? 0 : tr;
        size_t ia = base + (size_t)ta * DM_;
        size_t ir = base + (size_t)tr * DM_;
        w += (X[ia] + A[ia]) - (X[ir] + A[ir]);
    }
}

// ---------------- layernorm ----------------
__global__ void k_ln(const float* __restrict__ X, const float* __restrict__ g,
                     const float* __restrict__ be, float* __restrict__ Y) {
    int row = blockIdx.x, tid = threadIdx.x;
    __shared__ float buf[DM_];
    __shared__ float red[256];
    __shared__ float smu, sinv;
    const float* xr = X + (size_t)row * DM_;
    float s = 0.f;
    for (int i = tid; i < DM_; i += 256) { float v = xr[i]; buf[i] = v; s += v; }
    red[tid] = s; __syncthreads();
    for (int st = 128; st > 0; st >>= 1) { if (tid < st) red[tid] += red[tid+st]; __syncthreads(); }
    if (tid == 0) smu = red[0] * (1.0f/DM_);
    __syncthreads();
    float mu = smu, s2 = 0.f;
    for (int i = tid; i < DM_; i += 256) { float dv = buf[i] - mu; s2 += dv*dv; }
    red[tid] = s2; __syncthreads();
    for (int st = 128; st > 0; st >>= 1) { if (tid < st) red[tid] += red[tid+st]; __syncthreads(); }
    if (tid == 0) sinv = rsqrtf(red[0] * (1.0f/DM_) + 1e-5f);
    __syncthreads();
    float inv = sinv;
    for (int i = tid; i < DM_; i += 256)
        Y[(size_t)row*DM_ + i] = (buf[i] - mu) * inv * g[i] + be[i];
}

__global__ void k_submean(float* __restrict__ Y, int L) {
    int b = blockIdx.x, d = threadIdx.x;
    size_t base = (size_t)b * L * DM_ + d;
    float s = 0.f;
    for (int t = 0; t < L; t++) s += Y[base + (size_t)t*DM_];
    s *= (1.0f / L);
    for (int t = 0; t < L; t++) Y[base + (size_t)t*DM_] -= s;
}

// ---------------- final assembly ----------------
__global__ void k_final(const float* __restrict__ XLN, const float* __restrict__ TS,
                        const float* __restrict__ meanb, const float* __restrict__ Wt,
                        const float* __restrict__ Wp, const float* __restrict__ bp,
                        float* __restrict__ out) {
    int p = blockIdx.x, b = blockIdx.y, tid = threadIdx.x;
    int t = LBL_ + p;
    int r0 = (t - 1 + LD_) % LD_;
    int r2 = (t + 1) % LD_;
    float acc[NC_];
    #pragma unroll
    for (int c = 0; c < NC_; c++) acc[c] = 0.f;
    for (int d = tid; d < DM_; d += 256) {
        float xv  = XLN[((size_t)b*LD_ + t )*DM_ + d];
        float tv0 = TS [((size_t)b*LD_ + r0)*DM_ + d];
        float tv1 = TS [((size_t)b*LD_ + t )*DM_ + d];
        float tv2 = TS [((size_t)b*LD_ + r2)*DM_ + d];
        #pragma unroll
        for (int c = 0; c < NC_; c++) {
            acc[c] += xv  * Wp[(size_t)d*NC_ + c]
                    + tv0 * Wt[((size_t)0*DM_ + d)*NC_ + c]
                    + tv1 * Wt[((size_t)1*DM_ + d)*NC_ + c]
                    + tv2 * Wt[((size_t)2*DM_ + d)*NC_ + c];
        }
    }
    __shared__ float red[256];
    for (int c = 0; c < NC_; c++) {
        red[tid] = acc[c]; __syncthreads();
        for (int st = 128; st > 0; st >>= 1) { if (tid < st) red[tid] += red[tid+st]; __syncthreads(); }
        if (tid == 0)
            out[((size_t)b*PRED_ + p)*NC_ + c] = red[0] + meanb[b*NC_ + c] + bp[c];
        __syncthreads();
    }
}

// ================= host orchestration =================
static bf *ABH, *ABL, *QBH, *QBL, *KBH, *KBL, *HBH, *HBL, *WBH, *WBL;

static inline void mma_w(const bf* Ah, const bf* Al, size_t woff,
                         float* C, bf* SH, bf* SL,
                         int M, int N, int K, const float* bias, int act) {
    dim3 g(N/128, M/128, 1);
    k_mma<<<g, 256, SMEM_SZ>>>(Ah, Al, WBH + woff, WBL + woff, C, SH, SL,
                               K, N, M, N, 0, 0, 0, bias, act);
}

extern "C" void kernel_launch(void* const* d_in, const int* in_sizes, int n_in,
                              void* d_out, int out_size) {
    const float* x_enc      = (const float*)d_in[0];
    const float* x_mark_enc = (const float*)d_in[1];
    const float* x_mark_dec = (const float*)d_in[3];
    const float* W_enc_emb  = (const float*)d_in[4];
    const float* W_mark_enc = (const float*)d_in[5];
    const float* W_dec_emb  = (const float*)d_in[6];
    const float* W_mark_dec = (const float*)d_in[7];
    const float* eW_attn    = (const float*)d_in[8];
    const float* eb_attn    = (const float*)d_in[9];
    const float* eW1        = (const float*)d_in[10];
    const float* eW2        = (const float*)d_in[11];
    const float* eg         = (const float*)d_in[12];
    const float* ebeta      = (const float*)d_in[13];
    const float* sW         = (const float*)d_in[14];
    const float* sb         = (const float*)d_in[15];
    const float* cW         = (const float*)d_in[16];
    const float* cb         = (const float*)d_in[17];
    const float* dW1        = (const float*)d_in[18];
    const float* dW2        = (const float*)d_in[19];
    const float* W_trend    = (const float*)d_in[20];
    const float* dg         = (const float*)d_in[21];
    const float* dbeta      = (const float*)d_in[22];
    const float* Wproj      = (const float*)d_in[23];
    const float* bproj      = (const float*)d_in[24];
    float* out = (float*)d_out;

    cudaFuncSetAttribute(k_mma, cudaFuncAttributeMaxDynamicSharedMemorySize, SMEM_SZ);

    float* ws = nullptr;
    cudaGetSymbolAddress((void**)&ws, g_ws);
    int* dly = nullptr;
    cudaGetSymbolAddress((void**)&dly, g_delay);
    cudaGetSymbolAddress((void**)&ABH, g_abh);
    cudaGetSymbolAddress((void**)&ABL, g_abl);
    cudaGetSymbolAddress((void**)&QBH, g_qbh);
    cudaGetSymbolAddress((void**)&QBL, g_qbl);
    cudaGetSymbolAddress((void**)&KBH, g_kbh);
    cudaGetSymbolAddress((void**)&KBL, g_kbl);
    cudaGetSymbolAddress((void**)&HBH, g_hbh);
    cudaGetSymbolAddress((void**)&HBL, g_hbl);
    cudaGetSymbolAddress((void**)&WBH, g_wbh);
    cudaGetSymbolAddress((void**)&WBL, g_wbl);

    float* XE   = ws + O_XE;
    float* XA   = ws + O_XA;
    float* XD   = ws + O_XD;
    float* Qb   = ws + O_Q;
    float* Kb   = ws + O_K;
    float* Vb   = ws + O_V;
    float* Tb   = ws + O_T;
    float* Gb   = ws + O_G;
    float* CORR = ws + O_CORR;
    float* ENC  = ws + O_ENC;
    float* TS   = ws + O_TS;
    float* SEA  = ws + O_SEA;
    float* MEANB= ws + O_MEAN;
    float* WGT  = ws + O_WGT;

    dim3 tb(32, 8);
    // ---- weight transpose + split (all up front) ----
    for (int l = 0; l < 2; l++) {
        for (int i = 0; i < 4; i++) {
            size_t so = (size_t)(l*4 + i)*DM_*DM_;
            k_cvtT<<<dim3(DM_/32, DM_/32), tb>>>(eW_attn + so, WBH + OW_EATT + so, WBL + OW_EATT + so, DM_, DM_);
        }
        k_cvtT<<<dim3(DFF_/32, DM_/32), tb>>>(eW1 + (size_t)l*DM_*DFF_,
                WBH + OW_EW1 + (size_t)l*DM_*DFF_, WBL + OW_EW1 + (size_t)l*DM_*DFF_, DM_, DFF_);
        k_cvtT<<<dim3(DM_/32, DFF_/32), tb>>>(eW2 + (size_t)l*DFF_*DM_,
                WBH + OW_EW2 + (size_t)l*DFF_*DM_, WBL + OW_EW2 + (size_t)l*DFF_*DM_, DFF_, DM_);
    }
    for (int i = 0; i < 4; i++) {
        size_t so = (size_t)i*DM_*DM_;
        k_cvtT<<<dim3(DM_/32, DM_/32), tb>>>(sW + so, WBH + OW_SW + so, WBL + OW_SW + so, DM_, DM_);
        k_cvtT<<<dim3(DM_/32, DM_/32), tb>>>(cW + so, WBH + OW_CW + so, WBL + OW_CW + so, DM_, DM_);
    }
    k_cvtT<<<dim3(DFF_/32, DM_/32), tb>>>(dW1, WBH + OW_DW1, WBL + OW_DW1, DM_, DFF_);
    k_cvtT<<<dim3(DM_/32, DFF_/32), tb>>>(dW2, WBH + OW_DW2, WBL + OW_DW2, DFF_, DM_);

    // ---- prep ----
    k_sea<<<(B_*LE_*NC_ + 255)/256, 256>>>(x_enc, SEA);
    k_meanc<<<1, 256>>>(x_enc, MEANB);
    k_embed_enc<<<dim3(LE_, B_), DM_>>>(x_enc, x_mark_enc, W_enc_emb, W_mark_enc, XE);
    k_cvt<<<(B_*LE_*DM_ + 255)/256, 256>>>(XE, ABH, ABL, B_*LE_*DM_);

    // ---- encoder: 2 layers ----
    float* x = XE;
    for (int l = 0; l < 2; l++) {
        const float* bb = eb_attn + (size_t)l*4*DM_;
        size_t wa = OW_EATT + (size_t)l*4*DM_*DM_;
        // Q,K -> split only; V -> fp32
        mma_w(ABH, ABL, wa + 0*(size_t)DM_*DM_, nullptr, QBH, QBL, B_*LE_, DM_, DM_, bb + 0*DM_, 0);
        mma_w(ABH, ABL, wa + 1*(size_t)DM_*DM_, nullptr, KBH, KBL, B_*LE_, DM_, DM_, bb + 1*DM_, 0);
        mma_w(ABH, ABL, wa + 2*(size_t)DM_*DM_, Vb, nullptr, nullptr, B_*LE_, DM_, DM_, bb + 2*DM_, 0);
        k_mma<<<dim3(4, 4, B_), 256, SMEM_SZ>>>(QBH, QBL, KBH, KBL, Gb, nullptr, nullptr,
            DM_, LE_, LE_, LE_, (long long)LE_*DM_, (long long)LE_*DM_, (long long)LE_*LE_, nullptr, 0);
        k_corr<<<dim3(LE_, B_), 256>>>(Gb, CORR, LE_, LE_*LE_);
        k_topk<<<B_, 256>>>(CORR, LE_, KT_E, dly, WGT);
        k_agg<<<dim3(LE_, B_), DM_>>>(Vb, dly, WGT, ABH, ABL, LE_, LE_, KT_E, LE_*DM_);
        mma_w(ABH, ABL, wa + 3*(size_t)DM_*DM_, Tb, nullptr, nullptr, B_*LE_, DM_, DM_, bb + 3*DM_, 0);
        float* nx = (x == XE) ? XA : XE;
        k_add_decomp<<<dim3(8, B_), DM_>>>(x, Tb, nx, nullptr, ABH, ABL, LE_, 0);
        x = nx;
        mma_w(ABH, ABL, OW_EW1 + (size_t)l*DM_*DFF_, nullptr, HBH, HBL, B_*LE_, DFF_, DM_, nullptr, 1);
        mma_w(HBH, HBL, OW_EW2 + (size_t)l*DFF_*DM_, Tb, nullptr, nullptr, B_*LE_, DM_, DFF_, nullptr, 0);
        nx = (x == XE) ? XA : XE;
        k_add_decomp<<<dim3(8, B_), DM_>>>(x, Tb, nx, nullptr, ABH, ABL, LE_, 0);
        x = nx;
    }
    k_ln<<<B_*LE_, 256>>>(x, eg, ebeta, ENC);
    k_submean<<<B_, DM_>>>(ENC, LE_);

    // ---- decoder ----
    k_embed_dec<<<dim3(LD_, B_), DM_>>>(SEA, x_mark_enc, x_mark_dec, W_dec_emb, W_mark_dec, XD);
    k_cvt<<<(B_*LD_*DM_ + 255)/256, 256>>>(XD, ABH, ABL, B_*LD_*DM_);
    float* xd = XD;

    // self attention
    mma_w(ABH, ABL, OW_SW + 0*(size_t)DM_*DM_, Qb, nullptr, nullptr, B_*LD_, DM_, DM_, sb + 0*DM_, 0);
    mma_w(ABH, ABL, OW_SW + 1*(size_t)DM_*DM_, Kb, nullptr, nullptr, B_*LD_, DM_, DM_, sb + 1*DM_, 0);
    mma_w(ABH, ABL, OW_SW + 2*(size_t)DM_*DM_, Vb, nullptr, nullptr, B_*LD_, DM_, DM_, sb + 2*DM_, 0);
    k_cvt_pad<<<(B_*LP_*DM_ + 255)/256, 256>>>(Qb, QBH, QBL, LD_, LP_);
    k_cvt_pad<<<(B_*LP_*DM_ + 255)/256, 256>>>(Kb, KBH, KBL, LD_, LP_);
    k_mma<<<dim3(5, 5, B_), 256, SMEM_SZ>>>(QBH, QBL, KBH, KBL, Gb, nullptr, nullptr,
        DM_, LD_, LD_, LD_, (long long)LP_*DM_, (long long)LP_*DM_, (long long)LD_*LD_, nullptr, 0);
    k_corr<<<dim3(LD_, B_), 256>>>(Gb, CORR, LD_, LD_*LD_);
    k_topk<<<B_, 256>>>(CORR, LD_, KT_D, dly, WGT);
    k_agg<<<dim3(LD_, B_), DM_>>>(Vb, dly, WGT, ABH, ABL, LD_, LD_, KT_D, LD_*DM_);
    mma_w(ABH, ABL, OW_SW + 3*(size_t)DM_*DM_, Tb, nullptr, nullptr, B_*LD_, DM_, DM_, sb + 3*DM_, 0);
    k_add_decomp<<<dim3(8, B_), DM_>>>(xd, Tb, XA, TS, ABH, ABL, LD_, 1);
    xd = XA;

    // cross attention (K/V from enc_out; K zero-padded 512->640)
    mma_w(ABH, ABL, OW_CW + 0*(size_t)DM_*DM_, Qb, nullptr, nullptr, B_*LD_, DM_, DM_, cb + 0*DM_, 0);
    k_cvt<<<(B_*LE_*DM_ + 255)/256, 256>>>(ENC, ABH, ABL, B_*LE_*DM_);
    mma_w(ABH, ABL, OW_CW + 1*(size_t)DM_*DM_, Kb, nullptr, nullptr, B_*LE_, DM_, DM_, cb + 1*DM_, 0);
    mma_w(ABH, ABL, OW_CW + 2*(size_t)DM_*DM_, Vb, nullptr, nullptr, B_*LE_, DM_, DM_, cb + 2*DM_, 0);
    k_cvt_pad<<<(B_*LP_*DM_ + 255)/256, 256>>>(Qb, QBH, QBL, LD_, LP_);
    k_cvt_pad<<<(B_*LP_*DM_ + 255)/256, 256>>>(Kb, KBH, KBL, LE_, LP_);
    k_mma<<<dim3(5, 5, B_), 256, SMEM_SZ>>>(QBH, QBL, KBH, KBL, Gb, nullptr, nullptr,
        DM_, LD_, LD_, LD_, (long long)LP_*DM_, (long long)LP_*DM_, (long long)LD_*LD_, nullptr, 0);
    k_corr<<<dim3(LD_, B_), 256>>>(Gb, CORR, LD_, LD_*LD_);
    k_topk<<<B_, 256>>>(CORR, LD_, KT_D, dly, WGT);
    k_agg<<<dim3(LD_, B_), DM_>>>(Vb, dly, WGT, ABH, ABL, LD_, LE_, KT_D, LE_*DM_);
    mma_w(ABH, ABL, OW_CW + 3*(size_t)DM_*DM_, Tb, nullptr, nullptr, B_*LD_, DM_, DM_, cb + 3*DM_, 0);
    k_add_decomp<<<dim3(8, B_), DM_>>>(xd, Tb, XD, TS, ABH, ABL, LD_, 2);
    xd = XD;

    // FFN
    mma_w(ABH, ABL, OW_DW1, nullptr, HBH, HBL, B_*LD_, DFF_, DM_, nullptr, 1);
    mma_w(HBH, HBL, OW_DW2, Tb, nullptr, nullptr, B_*LD_, DM_, DFF_, nullptr, 0);
    k_add_decomp<<<dim3(8, B_), DM_>>>(xd, Tb, XA, TS, ABH, ABL, LD_, 2);
    xd = XA;

    // final layernorm + output assembly
    k_ln<<<B_*LD_, 256>>>(xd, dg, dbeta, Qb);
    k_submean<<<B_, DM_>>>(Qb, LD_);
    k_final<<<dim3(PRED_, B_), 256>>>(Qb, TS, MEANB, W_trend, Wproj, bproj, out);
}

// round 8
// speedup vs baseline: 2.2564x; 1.0465x over previous
#include <cuda_runtime.h>
#include <cuda_bf16.h>
#include <math.h>
#include <float.h>
#include <stdint.h>

typedef __nv_bfloat16 bf;

// ---------------- problem constants ----------------
#define B_    32
#define LE_   512
#define LD_   592
#define LP_   640
#define DM_   512
#define DFF_  2048
#define NC_   7
#define NM_   4
#define LBL_  256
#define PRED_ 336
#define KT_E  18
#define KT_D  19

// ---------------- fp32 workspace ----------------
#define SZ_XE  ((size_t)B_*LE_*DM_)
#define SZ_XD  ((size_t)B_*LD_*DM_)
#define SZ_G   ((size_t)B_*LD_*LD_)

#define O_XE   ((size_t)0)
#define O_XA   (O_XE + SZ_XE)
#define O_XD   (O_XA + SZ_XD)
#define O_Q    (O_XD + SZ_XD)          // Q/K/V combined region: 3*SZ_XD floats
#define O_K    (O_Q  + SZ_XD)
#define O_V    (O_K  + SZ_XD)
#define O_T    (O_V  + SZ_XD)
#define O_G    (O_T  + SZ_XD)
#define O_CORR (O_G  + SZ_G)
#define O_ENC  (O_CORR + (size_t)B_*LD_)
#define O_TS   (O_ENC + SZ_XE)
#define O_SEA  (O_TS + SZ_XD)
#define O_MEAN (O_SEA + (size_t)B_*LE_*NC_)
#define O_WGT  (O_MEAN + (size_t)B_*NC_)
#define WS_TOTAL (O_WGT + (size_t)B_*32)

__device__ __align__(256) float g_ws[WS_TOTAL];
__device__ int g_delay[B_*32];

// ---------------- bf16 split workspace ----------------
#define SZ_AB  ((size_t)B_*LP_*DM_)
#define SZ_QB  ((size_t)B_*LP_*DM_)
#define SZ_KB  ((size_t)B_*LP_*DM_)
#define SZ_HB  ((size_t)B_*LD_*DFF_)
#define OW_EATT ((size_t)0)
#define OW_EW1  ((size_t)2097152)
#define OW_EW2  ((size_t)4194304)
#define OW_SW   ((size_t)6291456)
#define OW_CW   ((size_t)7340032)
#define OW_DW1  ((size_t)8388608)
#define OW_DW2  ((size_t)9437184)
#define SZ_WB   ((size_t)10485760)

__device__ __align__(256) bf g_abh[SZ_AB];
__device__ __align__(256) bf g_abl[SZ_AB];
__device__ __align__(256) bf g_qbh[SZ_QB];
__device__ __align__(256) bf g_qbl[SZ_QB];
__device__ __align__(256) bf g_kbh[SZ_KB];
__device__ __align__(256) bf g_kbl[SZ_KB];
__device__ __align__(256) bf g_hbh[SZ_HB];
__device__ __align__(256) bf g_hbl[SZ_HB];
__device__ __align__(256) bf g_wbh[SZ_WB];
__device__ __align__(256) bf g_wbl[SZ_WB];

// ---------------- helpers ----------------
__device__ __forceinline__ float gelu_exact(float v) {
    return 0.5f * v * (1.0f + erff(v * 0.70710678118654752440f));
}
__device__ __forceinline__ uint32_t s2u(const void* p){
    uint32_t a;
    asm("{ .reg .u64 t; cvta.to.shared.u64 t, %1; cvt.u32.u64 %0, t; }":"=r"(a):"l"(p));
    return a;
}
#define SWZ(o) ((o) ^ (((o)>>3)&0x70))

#define LDSM4(r, ad) \
    asm volatile("ldmatrix.sync.aligned.m8n8.x4.shared.b16 {%0,%1,%2,%3}, [%4];" \
        : "=r"((r)[0]), "=r"((r)[1]), "=r"((r)[2]), "=r"((r)[3]) : "r"(ad))

#define MMA16816(d, a, b0, b1) \
    asm volatile("mma.sync.aligned.m16n8k16.row.col.f32.bf16.bf16.f32 " \
        "{%0,%1,%2,%3}, {%4,%5,%6,%7}, {%8,%9}, {%0,%1,%2,%3};" \
        : "+f"((d)[0]), "+f"((d)[1]), "+f"((d)[2]), "+f"((d)[3]) \
        : "r"((a)[0]), "r"((a)[1]), "r"((a)[2]), "r"((a)[3]), "r"(b0), "r"(b1))

// ---------------- conversion kernels ----------------
__global__ void k_cvt(const float* __restrict__ X, bf* __restrict__ H,
                      bf* __restrict__ Lo, int n){
    int i = blockIdx.x*256 + threadIdx.x;
    if (i >= n) return;
    float x = X[i];
    bf h = __float2bfloat16(x);
    H[i] = h; Lo[i] = __float2bfloat16(x - __bfloat162float(h));
}

// src [B][Lv][ldx] (col window of width DM), dst padded [B][Lp][DM]
__global__ void k_cvt_pad(const float* __restrict__ X, int ldx,
                          bf* __restrict__ H, bf* __restrict__ Lo,
                          int Lv, int Lp){
    int i = blockIdx.x*256 + threadIdx.x;
    int total = B_*Lp*DM_;
    if (i >= total) return;
    int col = i & (DM_-1);
    int row = (i/DM_) % Lp;
    int b = i/(DM_*Lp);
    float x = 0.f;
    if (row < Lv) x = X[((size_t)b*Lv + row)*ldx + col];
    bf h = __float2bfloat16(x);
    H[i] = h; Lo[i] = __float2bfloat16(x - __bfloat162float(h));
}

// transpose + split: W[K][N] -> TH/TL [N][K]
__global__ void k_cvtT(const float* __restrict__ W, bf* __restrict__ TH,
                       bf* __restrict__ TL, int K, int N){
    __shared__ float t[32][33];
    int n0 = blockIdx.x*32, k0 = blockIdx.y*32;
    int tx = threadIdx.x, ty = threadIdx.y;
    #pragma unroll
    for (int i = 0; i < 32; i += 8)
        t[ty+i][tx] = W[(size_t)(k0+ty+i)*N + n0 + tx];
    __syncthreads();
    #pragma unroll
    for (int i = 0; i < 32; i += 8) {
        float x = t[tx][ty+i];
        bf h = __float2bfloat16(x);
        size_t o = (size_t)(n0+ty+i)*K + k0 + tx;
        TH[o] = h; TL[o] = __float2bfloat16(x - __bfloat162float(h));
    }
}

// ---------------- bf16x3 mma.sync GEMM v2 ----------------
// per-K-chunk: load Ah,Al,Bh,Bl (4 tiles, 64KB), compute 3 products, dbl-buffer.
#define SMEM_SZ 131072

__device__ __forceinline__ void ldchunk(uint32_t st,
    const bf* __restrict__ A_h, const bf* __restrict__ A_l, int lda,
    const bf* __restrict__ B_h, const bf* __restrict__ B_l, int ldb,
    int k0, int tid)
{
    const bf* srcs[4] = {A_h, A_l, B_h, B_l};
    const int lds[4] = {lda, lda, ldb, ldb};
    #pragma unroll
    for (int t = 0; t < 4; t++) {
        #pragma unroll
        for (int i = 0; i < 4; i++) {
            int idx = i*256 + tid;
            int row = idx >> 3, c16 = idx & 7;
            uint32_t dst = st + t*16384 + SWZ(row*128 + c16*16);
            const bf* src = srcs[t] + (size_t)row*lds[t] + k0 + c16*8;
            asm volatile("cp.async.cg.shared.global [%0], [%1], 16;\n"::"r"(dst),"l"(src));
        }
    }
    asm volatile("cp.async.commit_group;\n":::"memory");
}

__global__ void __launch_bounds__(256,1) k_mma(
    const bf* __restrict__ Ah, const bf* __restrict__ Al, int lda,
    const bf* __restrict__ Bh, const bf* __restrict__ Bl, int ldb,
    float* __restrict__ C, bf* __restrict__ SH, bf* __restrict__ SL, int ldc,
    int K, int rowsV, int colsV,
    long long aB, long long bB, long long cB,
    const float* __restrict__ bias, int act)
{
    extern __shared__ char smem[];
    uint32_t sb0 = s2u(smem);
    const int tid = threadIdx.x, lane = tid & 31, wid = tid >> 5;
    const int bn = blockIdx.x, bm = blockIdx.y, bz = blockIdx.z;
    const bf* Ah2 = Ah + (size_t)bz*aB + (size_t)bm*128*lda;
    const bf* Al2 = Al + (size_t)bz*aB + (size_t)bm*128*lda;
    const bf* Bh2 = Bh + (size_t)bz*bB + (size_t)bn*128*ldb;
    const bf* Bl2 = Bl + (size_t)bz*bB + (size_t)bn*128*ldb;
    if (C)  C  += (size_t)bz*cB;
    if (SH) { SH += (size_t)bz*cB; SL += (size_t)bz*cB; }

    float acc[4][4][4];
    #pragma unroll
    for (int i = 0; i < 4; i++)
        #pragma unroll
        for (int j = 0; j < 4; j++)
            #pragma unroll
            for (int q = 0; q < 4; q++) acc[i][j][q] = 0.f;

    const int KC = K >> 6;
    const int m0 = (wid & 1) << 6, n0 = (wid >> 1) << 5;

    ldchunk(sb0, Ah2, Al2, lda, Bh2, Bl2, ldb, 0, tid);

    for (int c = 0; c < KC; c++) {
        uint32_t st = sb0 + (uint32_t)(c & 1) * 65536u;
        if (c+1 < KC) {
            ldchunk(sb0 + (uint32_t)((c+1) & 1) * 65536u,
                    Ah2, Al2, lda, Bh2, Bl2, ldb, (c+1)*64, tid);
            asm volatile("cp.async.wait_group 1;\n":::"memory");
        } else {
            asm volatile("cp.async.wait_group 0;\n":::"memory");
        }
        __syncthreads();

        #pragma unroll
        for (int kk = 0; kk < 4; kk++) {
            uint32_t afh[4][4], afl[4][4], bfh[2][4], bfl[2][4];
            #pragma unroll
            for (int mt = 0; mt < 4; mt++) {
                int m = m0 + mt*16 + (lane & 15);
                int kb = kk*32 + ((lane >> 4) << 4);
                uint32_t off = SWZ(m*128 + kb);
                LDSM4(afh[mt], st + off);
                LDSM4(afl[mt], st + 16384u + off);
            }
            #pragma unroll
            for (int nt2 = 0; nt2 < 2; nt2++) {
                int g = lane >> 3;
                int n = n0 + nt2*16 + ((g >> 1) << 3) + (lane & 7);
                int kb = kk*32 + ((g & 1) << 4);
                uint32_t off = SWZ(n*128 + kb);
                LDSM4(bfh[nt2], st + 32768u + off);
                LDSM4(bfl[nt2], st + 49152u + off);
            }
            // AhBh
            #pragma unroll
            for (int mt = 0; mt < 4; mt++)
                #pragma unroll
                for (int nt = 0; nt < 4; nt++)
                    MMA16816(acc[mt][nt], afh[mt],
                             bfh[nt>>1][(nt&1)*2], bfh[nt>>1][(nt&1)*2+1]);
            // AhBl
            #pragma unroll
            for (int mt = 0; mt < 4; mt++)
                #pragma unroll
                for (int nt = 0; nt < 4; nt++)
                    MMA16816(acc[mt][nt], afh[mt],
                             bfl[nt>>1][(nt&1)*2], bfl[nt>>1][(nt&1)*2+1]);
            // AlBh
            #pragma unroll
            for (int mt = 0; mt < 4; mt++)
                #pragma unroll
                for (int nt = 0; nt < 4; nt++)
                    MMA16816(acc[mt][nt], afl[mt],
                             bfh[nt>>1][(nt&1)*2], bfh[nt>>1][(nt&1)*2+1]);
        }
        __syncthreads();
    }

    // epilogue
    const int gid = lane >> 2, tig = lane & 3;
    #pragma unroll
    for (int mt = 0; mt < 4; mt++) {
        #pragma unroll
        for (int h = 0; h < 2; h++) {
            int row = bm*128 + m0 + mt*16 + gid + h*8;
            if (row >= rowsV) continue;
            #pragma unroll
            for (int nt = 0; nt < 4; nt++) {
                int col = bn*128 + n0 + nt*8 + tig*2;
                if (col >= colsV) continue;
                float v0 = acc[mt][nt][h*2+0];
                float v1 = acc[mt][nt][h*2+1];
                if (bias) { v0 += bias[col]; v1 += bias[col+1]; }
                if (act)  { v0 = gelu_exact(v0); v1 = gelu_exact(v1); }
                size_t o = (size_t)row*ldc + col;
                if (C) *(float2*)(C + o) = make_float2(v0, v1);
                if (SH) {
                    bf h0 = __float2bfloat16(v0), h1 = __float2bfloat16(v1);
                    bf l0 = __float2bfloat16(v0 - __bfloat162float(h0));
                    bf l1 = __float2bfloat16(v1 - __bfloat162float(h1));
                    *(__nv_bfloat162*)(SH + o) = __nv_bfloat162(h0, h1);
                    *(__nv_bfloat162*)(SL + o) = __nv_bfloat162(l0, l1);
                }
            }
        }
    }
}

// ---------------- prep ----------------
__global__ void k_sea(const float* __restrict__ xe, float* __restrict__ sea) {
    int i = blockIdx.x * blockDim.x + threadIdx.x;
    if (i >= B_*LE_*NC_) return;
    int c = i % NC_;
    int t = (i / NC_) % LE_;
    int b = i / (NC_*LE_);
    float s = 0.f;
    #pragma unroll
    for (int j = -12; j <= 12; j++) {
        int tt = t + j; tt = tt < 0 ? 0 : (tt >= LE_ ? LE_-1 : tt);
        s += xe[((size_t)b*LE_ + tt)*NC_ + c];
    }
    sea[i] = xe[i] - s * (1.0f/25.0f);
}

__global__ void k_meanc(const float* __restrict__ xe, float* __restrict__ mb) {
    int i = threadIdx.x;
    if (i >= B_*NC_) return;
    int b = i / NC_, c = i % NC_;
    float s = 0.f;
    for (int t = 0; t < LE_; t++) s += xe[((size_t)b*LE_ + t)*NC_ + c];
    mb[i] = s * (1.0f/LE_);
}

// ---------------- embeds (write fp32 + split) ----------------
__global__ void k_embed_enc(const float* __restrict__ xe, const float* __restrict__ mk_in,
                            const float* __restrict__ Wemb, const float* __restrict__ Wm,
                            float* __restrict__ out, bf* __restrict__ H, bf* __restrict__ Lo) {
    int t = blockIdx.x, b = blockIdx.y, d = threadIdx.x;
    __shared__ float xv[21];
    __shared__ float mk[NM_];
    int tid = threadIdx.x;
    if (tid < 21) {
        int j = tid / NC_, c = tid % NC_;
        int r = (t - 1 + j + LE_) % LE_;
        xv[tid] = xe[((size_t)b*LE_ + r)*NC_ + c];
    } else if (tid < 21 + NM_) {
        int m = tid - 21;
        mk[m] = mk_in[((size_t)b*LE_ + t)*NM_ + m];
    }
    __syncthreads();
    float acc = 0.f;
    #pragma unroll
    for (int jc = 0; jc < 21; jc++) acc += xv[jc] * Wemb[(size_t)jc*DM_ + d];
    #pragma unroll
    for (int m = 0; m < NM_; m++) acc += mk[m] * Wm[(size_t)m*DM_ + d];
    size_t o = ((size_t)b*LE_ + t)*DM_ + d;
    out[o] = acc;
    bf h = __float2bfloat16(acc);
    H[o] = h; Lo[o] = __float2bfloat16(acc - __bfloat162float(h));
}

__global__ void k_embed_dec(const float* __restrict__ sea, const float* __restrict__ mk_enc,
                            const float* __restrict__ mk_dec,
                            const float* __restrict__ Wemb, const float* __restrict__ Wm,
                            float* __restrict__ out, bf* __restrict__ H, bf* __restrict__ Lo) {
    int t = blockIdx.x, b = blockIdx.y, d = threadIdx.x;
    __shared__ float xv[21];
    __shared__ float mk[NM_];
    int tid = threadIdx.x;
    if (tid < 21) {
        int j = tid / NC_, c = tid % NC_;
        int r = (t - 1 + j + LD_) % LD_;
        xv[tid] = (r < LBL_) ? sea[((size_t)b*LE_ + LBL_ + r)*NC_ + c] : 0.f;
    } else if (tid < 21 + NM_) {
        int m = tid - 21;
        mk[m] = (t < LBL_) ? mk_enc[((size_t)b*LE_ + LBL_ + t)*NM_ + m]
                           : mk_dec[((size_t)b*PRED_ + (t - LBL_))*NM_ + m];
    }
    __syncthreads();
    float acc = 0.f;
    #pragma unroll
    for (int jc = 0; jc < 21; jc++) acc += xv[jc] * Wemb[(size_t)jc*DM_ + d];
    #pragma unroll
    for (int m = 0; m < NM_; m++) acc += mk[m] * Wm[(size_t)m*DM_ + d];
    size_t o = ((size_t)b*LD_ + t)*DM_ + d;
    out[o] = acc;
    bf h = __float2bfloat16(acc);
    H[o] = h; Lo[o] = __float2bfloat16(acc - __bfloat162float(h));
}

// ---------------- mean_corr: coalesced scatter version ----------------
__global__ void k_zero(float* __restrict__ p, int n){
    int i = blockIdx.x*256 + threadIdx.x;
    if (i < n) p[i] = 0.f;
}

__global__ void k_corr2(const float* __restrict__ G, float* __restrict__ corr,
                        int L, int gbs) {
    int b = blockIdx.y, tid = threadIdx.x;
    int t0 = blockIdx.x * 16;
    __shared__ float cs[640];
    for (int i = tid; i < L; i += 256) cs[i] = 0.f;
    __syncthreads();
    const float* Gb = G + (size_t)b*gbs;
    int t1 = min(t0 + 16, L);
    for (int t = t0; t < t1; t++) {
        const float* row = Gb + (size_t)t*L;
        for (int j = tid; j < L; j += 256) {
            int tau = t - j; if (tau < 0) tau += L;
            atomicAdd(&cs[tau], row[j]);
        }
    }
    __syncthreads();
    for (int i = tid; i < L; i += 256)
        atomicAdd(&corr[(size_t)b*L + i], cs[i] * (1.0f/DM_));
}

// ---------------- exact top-k + softmax ----------------
__global__ void k_topk(const float* __restrict__ corr, int L, int KT,
                       int* __restrict__ delay, float* __restrict__ wgt) {
    int b = blockIdx.x, tid = threadIdx.x;
    __shared__ float vals[640];
    __shared__ float rv[256];
    __shared__ int ri[256];
    __shared__ float tv[32];
    __shared__ int tix[32];
    for (int i = tid; i < L; i += 256) vals[i] = corr[(size_t)b*L + i];
    __syncthreads();
    for (int kt = 0; kt < KT; kt++) {
        float bv = -FLT_MAX; int bi = 0x7fffffff;
        for (int i = tid; i < L; i += 256) {
            float v = vals[i];
            if (v > bv || (v == bv && i < bi)) { bv = v; bi = i; }
        }
        rv[tid] = bv; ri[tid] = bi; __syncthreads();
        for (int st = 128; st > 0; st >>= 1) {
            if (tid < st) {
                float v2 = rv[tid+st]; int i2 = ri[tid+st];
                if (v2 > rv[tid] || (v2 == rv[tid] && i2 < ri[tid])) { rv[tid] = v2; ri[tid] = i2; }
            }
            __syncthreads();
        }
        if (tid == 0) { tv[kt] = rv[0]; tix[kt] = ri[0]; vals[ri[0]] = -FLT_MAX; }
        __syncthreads();
    }
    if (tid == 0) {
        float mx = tv[0], s = 0.f;
        float e[32];
        for (int i = 0; i < KT; i++) { e[i] = expf(tv[i] - mx); s += e[i]; }
        float inv = 1.0f / s;
        for (int i = 0; i < KT; i++) {
            wgt[b*32 + i] = e[i] * inv;
            delay[b*32 + i] = tix[i];
        }
    }
}

// ---------------- weighted circular gather (strided V, split out) ------------
__global__ void k_agg(const float* __restrict__ V, int vld, const int* __restrict__ delay,
                      const float* __restrict__ wgt, bf* __restrict__ OH,
                      bf* __restrict__ OL, int L, int S, int KT, long long vbs) {
    int t = blockIdx.x, b = blockIdx.y, d = threadIdx.x;
    __shared__ int sd[32];
    __shared__ float sw[32];
    if (d < KT) { sd[d] = delay[b*32 + d]; sw[d] = wgt[b*32 + d]; }
    __syncthreads();
    float acc = 0.f;
    for (int i = 0; i < KT; i++) {
        int r = t + sd[i]; if (r >= L) r -= L;
        if (r < S) acc += sw[i] * V[(size_t)b*vbs + (size_t)r*vld + d];
    }
    size_t o = ((size_t)b*L + t)*DM_ + d;
    bf h = __float2bfloat16(acc);
    OH[o] = h; OL[o] = __float2bfloat16(acc - __bfloat162float(h));
}

// ---------------- fused residual add + series_decomp (+ split out) -----------
__global__ void k_add_decomp(const float* __restrict__ X, const float* __restrict__ A,
                             float* __restrict__ S, float* __restrict__ T,
                             bf* __restrict__ SH, bf* __restrict__ SL,
                             int L, int tmode) {
    int b = blockIdx.y, ch = blockIdx.x, d = threadIdx.x;
    int CH = (L + 7) / 8;
    int t0 = ch * CH, t1 = min(t0 + CH, L);
    if (t0 >= L) return;
    const size_t base = (size_t)b * L * DM_ + d;
    float w = 0.f;
    for (int j = -12; j <= 12; j++) {
        int tt = t0 + j; tt = tt < 0 ? 0 : (tt >= L ? L-1 : tt);
        size_t idx = base + (size_t)tt * DM_;
        w += X[idx] + A[idx];
    }
    for (int t = t0; t < t1; t++) {
        size_t idx = base + (size_t)t * DM_;
        float cur = X[idx] + A[idx];
        float m = w * (1.0f/25.0f);
        float sv = cur - m;
        S[idx] = sv;
        bf h = __float2bfloat16(sv);
        SH[idx] = h; SL[idx] = __float2bfloat16(sv - __bfloat162float(h));
        if (tmode == 1) T[idx] = m;
        else if (tmode == 2) T[idx] += m;
        int ta = t + 13; ta = ta >= L ? L-1 : ta;
        int tr = t - 12; tr = tr < 0 ? 0 : tr;
        size_t ia = base + (size_t)ta * DM_;
        size_t ir = base + (size_t)tr * DM_;
        w += (X[ia] + A[ia]) - (X[ir] + A[ir]);
    }
}

// ---------------- layernorm ----------------
__global__ void k_ln(const float* __restrict__ X, const float* __restrict__ g,
                     const float* __restrict__ be, float* __restrict__ Y) {
    int row = blockIdx.x, tid = threadIdx.x;
    __shared__ float buf[DM_];
    __shared__ float red[256];
    __shared__ float smu, sinv;
    const float* xr = X + (size_t)row * DM_;
    float s = 0.f;
    for (int i = tid; i < DM_; i += 256) { float v = xr[i]; buf[i] = v; s += v; }
    red[tid] = s; __syncthreads();
    for (int st = 128; st > 0; st >>= 1) { if (tid < st) red[tid] += red[tid+st]; __syncthreads(); }
    if (tid == 0) smu = red[0] * (1.0f/DM_);
    __syncthreads();
    float mu = smu, s2 = 0.f;
    for (int i = tid; i < DM_; i += 256) { float dv = buf[i] - mu; s2 += dv*dv; }
    red[tid] = s2; __syncthreads();
    for (int st = 128; st > 0; st >>= 1) { if (tid < st) red[tid] += red[tid+st]; __syncthreads(); }
    if (tid == 0) sinv = rsqrtf(red[0] * (1.0f/DM_) + 1e-5f);
    __syncthreads();
    float inv = sinv;
    for (int i = tid; i < DM_; i += 256)
        Y[(size_t)row*DM_ + i] = (buf[i] - mu) * inv * g[i] + be[i];
}

__global__ void k_submean(float* __restrict__ Y, int L) {
    int b = blockIdx.x, d = threadIdx.x;
    size_t base = (size_t)b * L * DM_ + d;
    float s = 0.f;
    for (int t = 0; t < L; t++) s += Y[base + (size_t)t*DM_];
    s *= (1.0f / L);
    for (int t = 0; t < L; t++) Y[base + (size_t)t*DM_] -= s;
}

// ---------------- final assembly ----------------
__global__ void k_final(const float* __restrict__ XLN, const float* __restrict__ TS,
                        const float* __restrict__ meanb, const float* __restrict__ Wt,
                        const float* __restrict__ Wp, const float* __restrict__ bp,
                        float* __restrict__ out) {
    int p = blockIdx.x, b = blockIdx.y, tid = threadIdx.x;
    int t = LBL_ + p;
    int r0 = (t - 1 + LD_) % LD_;
    int r2 = (t + 1) % LD_;
    float acc[NC_];
    #pragma unroll
    for (int c = 0; c < NC_; c++) acc[c] = 0.f;
    for (int d = tid; d < DM_; d += 256) {
        float xv  = XLN[((size_t)b*LD_ + t )*DM_ + d];
        float tv0 = TS [((size_t)b*LD_ + r0)*DM_ + d];
        float tv1 = TS [((size_t)b*LD_ + t )*DM_ + d];
        float tv2 = TS [((size_t)b*LD_ + r2)*DM_ + d];
        #pragma unroll
        for (int c = 0; c < NC_; c++) {
            acc[c] += xv  * Wp[(size_t)d*NC_ + c]
                    + tv0 * Wt[((size_t)0*DM_ + d)*NC_ + c]
                    + tv1 * Wt[((size_t)1*DM_ + d)*NC_ + c]
                    + tv2 * Wt[((size_t)2*DM_ + d)*NC_ + c];
        }
    }
    __shared__ float red[256];
    for (int c = 0; c < NC_; c++) {
        red[tid] = acc[c]; __syncthreads();
        for (int st = 128; st > 0; st >>= 1) { if (tid < st) red[tid] += red[tid+st]; __syncthreads(); }
        if (tid == 0)
            out[((size_t)b*PRED_ + p)*NC_ + c] = red[0] + meanb[b*NC_ + c] + bp[c];
        __syncthreads();
    }
}

// ================= host orchestration =================
static bf *ABH, *ABL, *QBH, *QBL, *KBH, *KBL, *HBH, *HBL, *WBH, *WBL;

static inline void mma_w(const bf* Ah, const bf* Al, size_t woff,
                         float* C, bf* SH, bf* SL, int ldc,
                         int M, int N, int K, const float* bias, int act) {
    dim3 g(N/128, M/128, 1);
    k_mma<<<g, 256, SMEM_SZ>>>(Ah, Al, K, WBH + woff, WBL + woff, K,
                               C, SH, SL, ldc, K, M, N, 0, 0, 0, bias, act);
}

extern "C" void kernel_launch(void* const* d_in, const int* in_sizes, int n_in,
                              void* d_out, int out_size) {
    const float* x_enc      = (const float*)d_in[0];
    const float* x_mark_enc = (const float*)d_in[1];
    const float* x_mark_dec = (const float*)d_in[3];
    const float* W_enc_emb  = (const float*)d_in[4];
    const float* W_mark_enc = (const float*)d_in[5];
    const float* W_dec_emb  = (const float*)d_in[6];
    const float* W_mark_dec = (const float*)d_in[7];
    const float* eW_attn    = (const float*)d_in[8];
    const float* eb_attn    = (const float*)d_in[9];
    const float* eW1        = (const float*)d_in[10];
    const float* eW2        = (const float*)d_in[11];
    const float* eg         = (const float*)d_in[12];
    const float* ebeta      = (const float*)d_in[13];
    const float* sW         = (const float*)d_in[14];
    const float* sb         = (const float*)d_in[15];
    const float* cW         = (const float*)d_in[16];
    const float* cb         = (const float*)d_in[17];
    const float* dW1        = (const float*)d_in[18];
    const float* dW2        = (const float*)d_in[19];
    const float* W_trend    = (const float*)d_in[20];
    const float* dg         = (const float*)d_in[21];
    const float* dbeta      = (const float*)d_in[22];
    const float* Wproj      = (const float*)d_in[23];
    const float* bproj      = (const float*)d_in[24];
    float* out = (float*)d_out;

    cudaFuncSetAttribute(k_mma, cudaFuncAttributeMaxDynamicSharedMemorySize, SMEM_SZ);

    float* ws = nullptr;
    cudaGetSymbolAddress((void**)&ws, g_ws);
    int* dly = nullptr;
    cudaGetSymbolAddress((void**)&dly, g_delay);
    cudaGetSymbolAddress((void**)&ABH, g_abh);
    cudaGetSymbolAddress((void**)&ABL, g_abl);
    cudaGetSymbolAddress((void**)&QBH, g_qbh);
    cudaGetSymbolAddress((void**)&QBL, g_qbl);
    cudaGetSymbolAddress((void**)&KBH, g_kbh);
    cudaGetSymbolAddress((void**)&KBL, g_kbl);
    cudaGetSymbolAddress((void**)&HBH, g_hbh);
    cudaGetSymbolAddress((void**)&HBL, g_hbl);
    cudaGetSymbolAddress((void**)&WBH, g_wbh);
    cudaGetSymbolAddress((void**)&WBL, g_wbl);

    float* XE   = ws + O_XE;
    float* XA   = ws + O_XA;
    float* XD   = ws + O_XD;
    float* QKV  = ws + O_Q;      // merged [M][1536] region (3 slots)
    float* Qb   = ws + O_Q;      // standalone Q [M][512]
    float* KVb  = ws + O_K;      // merged cross KV [B*LE][1024]
    float* Tb   = ws + O_T;
    float* Gb   = ws + O_G;
    float* CORR = ws + O_CORR;
    float* ENC  = ws + O_ENC;
    float* TS   = ws + O_TS;
    float* SEA  = ws + O_SEA;
    float* MEANB= ws + O_MEAN;
    float* WGT  = ws + O_WGT;

    dim3 tb(32, 8);
    // ---- weight transpose + split ----
    for (int l = 0; l < 2; l++) {
        for (int i = 0; i < 4; i++) {
            size_t so = (size_t)(l*4 + i)*DM_*DM_;
            k_cvtT<<<dim3(DM_/32, DM_/32), tb>>>(eW_attn + so, WBH + OW_EATT + so, WBL + OW_EATT + so, DM_, DM_);
        }
        k_cvtT<<<dim3(DFF_/32, DM_/32), tb>>>(eW1 + (size_t)l*DM_*DFF_,
                WBH + OW_EW1 + (size_t)l*DM_*DFF_, WBL + OW_EW1 + (size_t)l*DM_*DFF_, DM_, DFF_);
        k_cvtT<<<dim3(DM_/32, DFF_/32), tb>>>(eW2 + (size_t)l*DFF_*DM_,
                WBH + OW_EW2 + (size_t)l*DFF_*DM_, WBL + OW_EW2 + (size_t)l*DFF_*DM_, DFF_, DM_);
    }
    for (int i = 0; i < 4; i++) {
        size_t so = (size_t)i*DM_*DM_;
        k_cvtT<<<dim3(DM_/32, DM_/32), tb>>>(sW + so, WBH + OW_SW + so, WBL + OW_SW + so, DM_, DM_);
        k_cvtT<<<dim3(DM_/32, DM_/32), tb>>>(cW + so, WBH + OW_CW + so, WBL + OW_CW + so, DM_, DM_);
    }
    k_cvtT<<<dim3(DFF_/32, DM_/32), tb>>>(dW1, WBH + OW_DW1, WBL + OW_DW1, DM_, DFF_);
    k_cvtT<<<dim3(DM_/32, DFF_/32), tb>>>(dW2, WBH + OW_DW2, WBL + OW_DW2, DFF_, DM_);

    // ---- prep ----
    k_sea<<<(B_*LE_*NC_ + 255)/256, 256>>>(x_enc, SEA);
    k_meanc<<<1, 256>>>(x_enc, MEANB);
    k_embed_enc<<<dim3(LE_, B_), DM_>>>(x_enc, x_mark_enc, W_enc_emb, W_mark_enc, XE, ABH, ABL);

    const int NPADE = (B_*LE_*DM_ + 255)/256;   // enc cvt grid (Lp=LE)
    const int NPADD = (B_*LP_*DM_ + 255)/256;   // dec padded cvt grid

    // ---- encoder: 2 layers ----
    float* x = XE;
    for (int l = 0; l < 2; l++) {
        const float* bb = eb_attn + (size_t)l*4*DM_;
        size_t wa = OW_EATT + (size_t)l*4*DM_*DM_;
        // merged QKV projection: N=1536
        mma_w(ABH, ABL, wa, QKV, nullptr, nullptr, 1536, B_*LE_, 1536, DM_, bb, 0);
        k_cvt_pad<<<NPADE, 256>>>(QKV,       1536, QBH, QBL, LE_, LE_);
        k_cvt_pad<<<NPADE, 256>>>(QKV + 512, 1536, KBH, KBL, LE_, LE_);
        k_mma<<<dim3(4, 4, B_), 256, SMEM_SZ>>>(QBH, QBL, DM_, KBH, KBL, DM_,
            Gb, nullptr, nullptr, LE_, DM_, LE_, LE_,
            (long long)LE_*DM_, (long long)LE_*DM_, (long long)LE_*LE_, nullptr, 0);
        k_zero<<<(B_*LE_ + 255)/256, 256>>>(CORR, B_*LE_);
        k_corr2<<<dim3(LE_/16, B_), 256>>>(Gb, CORR, LE_, LE_*LE_);
        k_topk<<<B_, 256>>>(CORR, LE_, KT_E, dly, WGT);
        k_agg<<<dim3(LE_, B_), DM_>>>(QKV + 1024, 1536, dly, WGT, ABH, ABL,
                                      LE_, LE_, KT_E, (long long)LE_*1536);
        mma_w(ABH, ABL, wa + 3*(size_t)DM_*DM_, Tb, nullptr, nullptr, DM_,
              B_*LE_, DM_, DM_, bb + 3*DM_, 0);
        float* nx = (x == XE) ? XA : XE;
        k_add_decomp<<<dim3(8, B_), DM_>>>(x, Tb, nx, nullptr, ABH, ABL, LE_, 0);
        x = nx;
        mma_w(ABH, ABL, OW_EW1 + (size_t)l*DM_*DFF_, nullptr, HBH, HBL, DFF_,
              B_*LE_, DFF_, DM_, nullptr, 1);
        mma_w(HBH, HBL, OW_EW2 + (size_t)l*DFF_*DM_, Tb, nullptr, nullptr, DM_,
              B_*LE_, DM_, DFF_, nullptr, 0);
        nx = (x == XE) ? XA : XE;
        k_add_decomp<<<dim3(8, B_), DM_>>>(x, Tb, nx, nullptr, ABH, ABL, LE_, 0);
        x = nx;
    }
    k_ln<<<B_*LE_, 256>>>(x, eg, ebeta, ENC);
    k_submean<<<B_, DM_>>>(ENC, LE_);

    // ---- decoder ----
    k_embed_dec<<<dim3(LD_, B_), DM_>>>(SEA, x_mark_enc, x_mark_dec, W_dec_emb, W_mark_dec, XD, ABH, ABL);
    float* xd = XD;

    // self attention (merged QKV, N=1536)
    mma_w(ABH, ABL, OW_SW, QKV, nullptr, nullptr, 1536, B_*LD_, 1536, DM_, sb, 0);
    k_cvt_pad<<<NPADD, 256>>>(QKV,       1536, QBH, QBL, LD_, LP_);
    k_cvt_pad<<<NPADD, 256>>>(QKV + 512, 1536, KBH, KBL, LD_, LP_);
    k_mma<<<dim3(5, 5, B_), 256, SMEM_SZ>>>(QBH, QBL, DM_, KBH, KBL, DM_,
        Gb, nullptr, nullptr, LD_, DM_, LD_, LD_,
        (long long)LP_*DM_, (long long)LP_*DM_, (long long)LD_*LD_, nullptr, 0);
    k_zero<<<(B_*LD_ + 255)/256, 256>>>(CORR, B_*LD_);
    k_corr2<<<dim3((LD_+15)/16, B_), 256>>>(Gb, CORR, LD_, LD_*LD_);
    k_topk<<<B_, 256>>>(CORR, LD_, KT_D, dly, WGT);
    k_agg<<<dim3(LD_, B_), DM_>>>(QKV + 1024, 1536, dly, WGT, ABH, ABL,
                                  LD_, LD_, KT_D, (long long)LD_*1536);
    mma_w(ABH, ABL, OW_SW + 3*(size_t)DM_*DM_, Tb, nullptr, nullptr, DM_,
          B_*LD_, DM_, DM_, sb + 3*DM_, 0);
    k_add_decomp<<<dim3(8, B_), DM_>>>(xd, Tb, XA, TS, ABH, ABL, LD_, 1);
    xd = XA;

    // cross attention: Q from x, K/V merged from enc_out
    mma_w(ABH, ABL, OW_CW, Qb, nullptr, nullptr, DM_, B_*LD_, DM_, DM_, cb, 0);
    k_cvt<<<NPADE, 256>>>(ENC, ABH, ABL, B_*LE_*DM_);
    mma_w(ABH, ABL, OW_CW + (size_t)DM_*DM_, KVb, nullptr, nullptr, 1024,
          B_*LE_, 1024, DM_, cb + DM_, 0);
    k_cvt_pad<<<NPADD, 256>>>(Qb,  512,  QBH, QBL, LD_, LP_);
    k_cvt_pad<<<NPADD, 256>>>(KVb, 1024, KBH, KBL, LE_, LP_);   // rows>=512 zero
    k_mma<<<dim3(5, 5, B_), 256, SMEM_SZ>>>(QBH, QBL, DM_, KBH, KBL, DM_,
        Gb, nullptr, nullptr, LD_, DM_, LD_, LD_,
        (long long)LP_*DM_, (long long)LP_*DM_, (long long)LD_*LD_, nullptr, 0);
    k_zero<<<(B_*LD_ + 255)/256, 256>>>(CORR, B_*LD_);
    k_corr2<<<dim3((LD_+15)/16, B_), 256>>>(Gb, CORR, LD_, LD_*LD_);
    k_topk<<<B_, 256>>>(CORR, LD_, KT_D, dly, WGT);
    k_agg<<<dim3(LD_, B_), DM_>>>(KVb + 512, 1024, dly, WGT, ABH, ABL,
                                  LD_, LE_, KT_D, (long long)LE_*1024);
    mma_w(ABH, ABL, OW_CW + 3*(size_t)DM_*DM_, Tb, nullptr, nullptr, DM_,
          B_*LD_, DM_, DM_, cb + 3*DM_, 0);
    k_add_decomp<<<dim3(8, B_), DM_>>>(xd, Tb, XD, TS, ABH, ABL, LD_, 2);
    xd = XD;

    // FFN
    mma_w(ABH, ABL, OW_DW1, nullptr, HBH, HBL, DFF_, B_*LD_, DFF_, DM_, nullptr, 1);
    mma_w(HBH, HBL, OW_DW2, Tb, nullptr, nullptr, DM_, B_*LD_, DM_, DFF_, nullptr, 0);
    k_add_decomp<<<dim3(8, B_), DM_>>>(xd, Tb, XA, TS, ABH, ABL, LD_, 2);
    xd = XA;

    // final layernorm + output assembly
    k_ln<<<B_*LD_, 256>>>(xd, dg, dbeta, Qb);
    k_submean<<<B_, DM_>>>(Qb, LD_);
    k_final<<<dim3(PRED_, B_), 256>>>(Qb, TS, MEANB, W_trend, Wproj, bproj, out);
}

// round 9
// speedup vs baseline: 2.3122x; 1.0247x over previous
#include <cuda_runtime.h>
#include <cuda_bf16.h>
#include <math.h>
#include <float.h>
#include <stdint.h>

typedef __nv_bfloat16 bf;

// ---------------- problem constants ----------------
#define B_    32
#define LE_   512
#define LD_   592
#define LP_   640
#define DM_   512
#define DFF_  2048
#define NC_   7
#define NM_   4
#define LBL_  256
#define PRED_ 336
#define KT_E  18
#define KT_D  19

// ---------------- fp32 workspace ----------------
#define SZ_XE  ((size_t)B_*LE_*DM_)
#define SZ_XD  ((size_t)B_*LD_*DM_)
#define SZ_G   ((size_t)B_*LD_*LD_)

#define O_XE   ((size_t)0)
#define O_XA   (O_XE + SZ_XE)
#define O_XD   (O_XA + SZ_XD)
#define O_Q    (O_XD + SZ_XD)
#define O_V    (O_Q  + SZ_XD)
#define O_T    (O_V  + SZ_XD)
#define O_G    (O_T  + SZ_XD)
#define O_CORR (O_G  + SZ_G)
#define O_ENC  (O_CORR + (size_t)B_*LD_)
#define O_TS   (O_ENC + SZ_XE)
#define O_SEA  (O_TS + SZ_XD)
#define O_MEAN (O_SEA + (size_t)B_*LE_*NC_)
#define O_WGT  (O_MEAN + (size_t)B_*NC_)
#define WS_TOTAL (O_WGT + (size_t)B_*32)

__device__ __align__(256) float g_ws[WS_TOTAL];
__device__ int g_delay[B_*32];

// ---------------- bf16 split workspace ----------------
#define SZ_AB  ((size_t)B_*LP_*DM_)
#define SZ_QB  ((size_t)B_*LP_*DM_)
#define SZ_KB  ((size_t)B_*LP_*DM_)
#define SZ_HB  ((size_t)B_*LD_*DFF_)
#define OW_EATT ((size_t)0)
#define OW_EW1  ((size_t)2097152)
#define OW_EW2  ((size_t)4194304)
#define OW_SW   ((size_t)6291456)
#define OW_CW   ((size_t)7340032)
#define OW_DW1  ((size_t)8388608)
#define OW_DW2  ((size_t)9437184)
#define SZ_WB   ((size_t)10485760)

__device__ __align__(256) bf g_abh[SZ_AB];
__device__ __align__(256) bf g_abl[SZ_AB];
__device__ __align__(256) bf g_qbh[SZ_QB];
__device__ __align__(256) bf g_qbl[SZ_QB];
__device__ __align__(256) bf g_kbh[SZ_KB];
__device__ __align__(256) bf g_kbl[SZ_KB];
__device__ __align__(256) bf g_hbh[SZ_HB];
__device__ __align__(256) bf g_hbl[SZ_HB];
__device__ __align__(256) bf g_wbh[SZ_WB];
__device__ __align__(256) bf g_wbl[SZ_WB];

// ---------------- helpers ----------------
__device__ __forceinline__ float gelu_exact(float v) {
    return 0.5f * v * (1.0f + erff(v * 0.70710678118654752440f));
}
__device__ __forceinline__ uint32_t s2u(const void* p){
    uint32_t a;
    asm("{ .reg .u64 t; cvta.to.shared.u64 t, %1; cvt.u32.u64 %0, t; }":"=r"(a):"l"(p));
    return a;
}
#define SWZ(o) ((o) ^ (((o)>>3)&0x70))

#define LDSM4(r, ad) \
    asm volatile("ldmatrix.sync.aligned.m8n8.x4.shared.b16 {%0,%1,%2,%3}, [%4];" \
        : "=r"((r)[0]), "=r"((r)[1]), "=r"((r)[2]), "=r"((r)[3]) : "r"(ad))

#define MMA16816(d, a, b0, b1) \
    asm volatile("mma.sync.aligned.m16n8k16.row.col.f32.bf16.bf16.f32 " \
        "{%0,%1,%2,%3}, {%4,%5,%6,%7}, {%8,%9}, {%0,%1,%2,%3};" \
        : "+f"((d)[0]), "+f"((d)[1]), "+f"((d)[2]), "+f"((d)[3]) \
        : "r"((a)[0]), "r"((a)[1]), "r"((a)[2]), "r"((a)[3]), "r"(b0), "r"(b1))

__device__ __forceinline__ void split_store(bf* H, bf* L, size_t o, float v0, float v1){
    bf h0 = __float2bfloat16(v0), h1 = __float2bfloat16(v1);
    bf l0 = __float2bfloat16(v0 - __bfloat162float(h0));
    bf l1 = __float2bfloat16(v1 - __bfloat162float(h1));
    *(__nv_bfloat162*)(H + o) = __nv_bfloat162(h0, h1);
    *(__nv_bfloat162*)(L + o) = __nv_bfloat162(l0, l1);
}

// ---------------- fused weight transpose+split: all matrices, one launch ----
// W[K][N] -> [N][K] split into WBH/WBL at fixed slot offsets.
__global__ void k_cvtT_all(const float* __restrict__ eatt, const float* __restrict__ e1,
                           const float* __restrict__ e2, const float* __restrict__ sw,
                           const float* __restrict__ cw, const float* __restrict__ d1,
                           const float* __restrict__ d2,
                           bf* __restrict__ WH, bf* __restrict__ WL){
    __shared__ float t[32][33];
    int blk = blockIdx.x;
    const float* src; size_t dstoff; int K, N, mi, tt;
    if (blk < 2048)       { src=eatt; dstoff=OW_EATT; K=512; N=512;  mi=blk/256;        tt=blk%256; }
    else if (blk < 4096)  { src=e1;   dstoff=OW_EW1;  K=512; N=2048; mi=(blk-2048)/1024; tt=(blk-2048)%1024; }
    else if (blk < 6144)  { src=e2;   dstoff=OW_EW2;  K=2048;N=512;  mi=(blk-4096)/1024; tt=(blk-4096)%1024; }
    else if (blk < 7168)  { src=sw;   dstoff=OW_SW;   K=512; N=512;  mi=(blk-6144)/256;  tt=(blk-6144)%256; }
    else if (blk < 8192)  { src=cw;   dstoff=OW_CW;   K=512; N=512;  mi=(blk-7168)/256;  tt=(blk-7168)%256; }
    else if (blk < 9216)  { src=d1;   dstoff=OW_DW1;  K=512; N=2048; mi=0;               tt=blk-8192; }
    else                  { src=d2;   dstoff=OW_DW2;  K=2048;N=512;  mi=0;               tt=blk-9216; }
    int tn = N/32;
    int n0 = (tt % tn)*32, k0 = (tt / tn)*32;
    const float* W = src + (size_t)mi*K*N;
    bf* TH = WH + dstoff + (size_t)mi*K*N;
    bf* TL = WL + dstoff + (size_t)mi*K*N;
    int tx = threadIdx.x, ty = threadIdx.y;
    #pragma unroll
    for (int i = 0; i < 32; i += 8)
        t[ty+i][tx] = W[(size_t)(k0+ty+i)*N + n0 + tx];
    __syncthreads();
    #pragma unroll
    for (int i = 0; i < 32; i += 8) {
        float x = t[tx][ty+i];
        bf h = __float2bfloat16(x);
        size_t o = (size_t)(n0+ty+i)*K + k0 + tx;
        TH[o] = h; TL[o] = __float2bfloat16(x - __bfloat162float(h));
    }
}

// ---------------- bf16x3 mma.sync GEMM, routed epilogue ----------------
// mode 0: C fp32 (ldc), with bz batch stride cB (Gram) or dense.
// mode 1: split H0/L0, row padded map (Lv->Lp), leading dim ldh0.
// mode 2/3: column-tile routing: [0,nq*128)->H0/L0 padded(ld 512);
//           [nq*128,(nq+nk)*128)->H1/L1 padded(ld 512); rest -> C fp32 (ldc) dense rows.
#define SMEM_SZ 131072

__device__ __forceinline__ void ldchunk(uint32_t st,
    const bf* __restrict__ A_h, const bf* __restrict__ A_l, int lda,
    const bf* __restrict__ B_h, const bf* __restrict__ B_l, int ldb,
    int k0, int tid)
{
    const bf* srcs[4] = {A_h, A_l, B_h, B_l};
    const int lds[4] = {lda, lda, ldb, ldb};
    #pragma unroll
    for (int t = 0; t < 4; t++) {
        #pragma unroll
        for (int i = 0; i < 4; i++) {
            int idx = i*256 + tid;
            int row = idx >> 3, c16 = idx & 7;
            uint32_t dst = st + t*16384 + SWZ(row*128 + c16*16);
            const bf* src = srcs[t] + (size_t)row*lds[t] + k0 + c16*8;
            asm volatile("cp.async.cg.shared.global [%0], [%1], 16;\n"::"r"(dst),"l"(src));
        }
    }
    asm volatile("cp.async.commit_group;\n":::"memory");
}

__global__ void __launch_bounds__(256,1) k_mma(
    const bf* __restrict__ Ah, const bf* __restrict__ Al, int lda,
    const bf* __restrict__ Bh, const bf* __restrict__ Bl, int ldb,
    int K, int rowsV, int colsV,
    long long aB, long long bB, long long cB,
    int mode, float* __restrict__ C, int ldc,
    bf* __restrict__ H0, bf* __restrict__ L0, int ldh0,
    bf* __restrict__ H1, bf* __restrict__ L1,
    int Lv, int Lp, int nq, int nk,
    const float* __restrict__ bias, int act)
{
    extern __shared__ char smem[];
    uint32_t sb0 = s2u(smem);
    const int tid = threadIdx.x, lane = tid & 31, wid = tid >> 5;
    const int bn = blockIdx.x, bm = blockIdx.y, bz = blockIdx.z;
    const bf* Ah2 = Ah + (size_t)bz*aB + (size_t)bm*128*lda;
    const bf* Al2 = Al + (size_t)bz*aB + (size_t)bm*128*lda;
    const bf* Bh2 = Bh + (size_t)bz*bB + (size_t)bn*128*ldb;
    const bf* Bl2 = Bl + (size_t)bz*bB + (size_t)bn*128*ldb;
    if (C) C += (size_t)bz*cB;

    float acc[4][4][4];
    #pragma unroll
    for (int i = 0; i < 4; i++)
        #pragma unroll
        for (int j = 0; j < 4; j++)
            #pragma unroll
            for (int q = 0; q < 4; q++) acc[i][j][q] = 0.f;

    const int KC = K >> 6;
    const int m0 = (wid & 1) << 6, n0 = (wid >> 1) << 5;

    ldchunk(sb0, Ah2, Al2, lda, Bh2, Bl2, ldb, 0, tid);

    for (int c = 0; c < KC; c++) {
        uint32_t st = sb0 + (uint32_t)(c & 1) * 65536u;
        if (c+1 < KC) {
            ldchunk(sb0 + (uint32_t)((c+1) & 1) * 65536u,
                    Ah2, Al2, lda, Bh2, Bl2, ldb, (c+1)*64, tid);
            asm volatile("cp.async.wait_group 1;\n":::"memory");
        } else {
            asm volatile("cp.async.wait_group 0;\n":::"memory");
        }
        __syncthreads();

        #pragma unroll
        for (int kk = 0; kk < 4; kk++) {
            uint32_t afh[4][4], afl[4][4], bfh[2][4], bfl[2][4];
            #pragma unroll
            for (int mt = 0; mt < 4; mt++) {
                int m = m0 + mt*16 + (lane & 15);
                int kb = kk*32 + ((lane >> 4) << 4);
                uint32_t off = SWZ(m*128 + kb);
                LDSM4(afh[mt], st + off);
                LDSM4(afl[mt], st + 16384u + off);
            }
            #pragma unroll
            for (int nt2 = 0; nt2 < 2; nt2++) {
                int g = lane >> 3;
                int n = n0 + nt2*16 + ((g >> 1) << 3) + (lane & 7);
                int kb = kk*32 + ((g & 1) << 4);
                uint32_t off = SWZ(n*128 + kb);
                LDSM4(bfh[nt2], st + 32768u + off);
                LDSM4(bfl[nt2], st + 49152u + off);
            }
            #pragma unroll
            for (int mt = 0; mt < 4; mt++)
                #pragma unroll
                for (int nt = 0; nt < 4; nt++)
                    MMA16816(acc[mt][nt], afh[mt],
                             bfh[nt>>1][(nt&1)*2], bfh[nt>>1][(nt&1)*2+1]);
            #pragma unroll
            for (int mt = 0; mt < 4; mt++)
                #pragma unroll
                for (int nt = 0; nt < 4; nt++)
                    MMA16816(acc[mt][nt], afh[mt],
                             bfl[nt>>1][(nt&1)*2], bfl[nt>>1][(nt&1)*2+1]);
            #pragma unroll
            for (int mt = 0; mt < 4; mt++)
                #pragma unroll
                for (int nt = 0; nt < 4; nt++)
                    MMA16816(acc[mt][nt], afl[mt],
                             bfh[nt>>1][(nt&1)*2], bfh[nt>>1][(nt&1)*2+1]);
        }
        __syncthreads();
    }

    // routed epilogue
    const int gid = lane >> 2, tig = lane & 3;
    const int nq128 = nq*128, nqk128 = (nq+nk)*128;
    #pragma unroll
    for (int mt = 0; mt < 4; mt++) {
        #pragma unroll
        for (int h = 0; h < 2; h++) {
            int row = bm*128 + m0 + mt*16 + gid + h*8;
            if (row >= rowsV) continue;
            int bq = row / Lv, rr = row - bq*Lv;
            size_t prow = (size_t)bq*Lp + rr;
            #pragma unroll
            for (int nt = 0; nt < 4; nt++) {
                int col = bn*128 + n0 + nt*8 + tig*2;
                if (col >= colsV) continue;
                float v0 = acc[mt][nt][h*2+0];
                float v1 = acc[mt][nt][h*2+1];
                if (bias) { v0 += bias[col]; v1 += bias[col+1]; }
                if (act)  { v0 = gelu_exact(v0); v1 = gelu_exact(v1); }
                if (mode == 0) {
                    *(float2*)(C + (size_t)row*ldc + col) = make_float2(v0, v1);
                } else if (mode == 1) {
                    split_store(H0, L0, prow*ldh0 + col, v0, v1);
                } else {
                    if (col < nq128)
                        split_store(H0, L0, prow*DM_ + col, v0, v1);
                    else if (col < nqk128)
                        split_store(H1, L1, prow*DM_ + (col - nq128), v0, v1);
                    else
                        *(float2*)(C + (size_t)row*ldc + (col - nqk128)) = make_float2(v0, v1);
                }
            }
        }
    }
}

// ---------------- prep ----------------
__global__ void k_sea(const float* __restrict__ xe, float* __restrict__ sea) {
    int i = blockIdx.x * blockDim.x + threadIdx.x;
    if (i >= B_*LE_*NC_) return;
    int c = i % NC_;
    int t = (i / NC_) % LE_;
    int b = i / (NC_*LE_);
    float s = 0.f;
    #pragma unroll
    for (int j = -12; j <= 12; j++) {
        int tt = t + j; tt = tt < 0 ? 0 : (tt >= LE_ ? LE_-1 : tt);
        s += xe[((size_t)b*LE_ + tt)*NC_ + c];
    }
    sea[i] = xe[i] - s * (1.0f/25.0f);
}

__global__ void k_meanc(const float* __restrict__ xe, float* __restrict__ mb) {
    int b = blockIdx.x, tid = threadIdx.x;
    __shared__ float red[7][32];
    if (tid < 224) {
        int c = tid % NC_, slot = tid / NC_;
        float s = 0.f;
        for (int t = slot; t < LE_; t += 32) s += xe[((size_t)b*LE_ + t)*NC_ + c];
        red[c][slot] = s;
    }
    __syncthreads();
    if (tid < NC_) {
        float s = 0.f;
        #pragma unroll
        for (int j = 0; j < 32; j++) s += red[tid][j];
        mb[b*NC_ + tid] = s * (1.0f/LE_);
    }
}

// ---------------- embeds (write fp32 + split) ----------------
__global__ void k_embed_enc(const float* __restrict__ xe, const float* __restrict__ mk_in,
                            const float* __restrict__ Wemb, const float* __restrict__ Wm,
                            float* __restrict__ out, bf* __restrict__ H, bf* __restrict__ Lo) {
    int t = blockIdx.x, b = blockIdx.y, d = threadIdx.x;
    __shared__ float xv[21];
    __shared__ float mk[NM_];
    int tid = threadIdx.x;
    if (tid < 21) {
        int j = tid / NC_, c = tid % NC_;
        int r = (t - 1 + j + LE_) % LE_;
        xv[tid] = xe[((size_t)b*LE_ + r)*NC_ + c];
    } else if (tid < 21 + NM_) {
        int m = tid - 21;
        mk[m] = mk_in[((size_t)b*LE_ + t)*NM_ + m];
    }
    __syncthreads();
    float acc = 0.f;
    #pragma unroll
    for (int jc = 0; jc < 21; jc++) acc += xv[jc] * Wemb[(size_t)jc*DM_ + d];
    #pragma unroll
    for (int m = 0; m < NM_; m++) acc += mk[m] * Wm[(size_t)m*DM_ + d];
    size_t o = ((size_t)b*LE_ + t)*DM_ + d;
    out[o] = acc;
    bf h = __float2bfloat16(acc);
    H[o] = h; Lo[o] = __float2bfloat16(acc - __bfloat162float(h));
}

__global__ void k_embed_dec(const float* __restrict__ sea, const float* __restrict__ mk_enc,
                            const float* __restrict__ mk_dec,
                            const float* __restrict__ Wemb, const float* __restrict__ Wm,
                            float* __restrict__ out, bf* __restrict__ H, bf* __restrict__ Lo) {
    int t = blockIdx.x, b = blockIdx.y, d = threadIdx.x;
    __shared__ float xv[21];
    __shared__ float mk[NM_];
    int tid = threadIdx.x;
    if (tid < 21) {
        int j = tid / NC_, c = tid % NC_;
        int r = (t - 1 + j + LD_) % LD_;
        xv[tid] = (r < LBL_) ? sea[((size_t)b*LE_ + LBL_ + r)*NC_ + c] : 0.f;
    } else if (tid < 21 + NM_) {
        int m = tid - 21;
        mk[m] = (t < LBL_) ? mk_enc[((size_t)b*LE_ + LBL_ + t)*NM_ + m]
                           : mk_dec[((size_t)b*PRED_ + (t - LBL_))*NM_ + m];
    }
    __syncthreads();
    float acc = 0.f;
    #pragma unroll
    for (int jc = 0; jc < 21; jc++) acc += xv[jc] * Wemb[(size_t)jc*DM_ + d];
    #pragma unroll
    for (int m = 0; m < NM_; m++) acc += mk[m] * Wm[(size_t)m*DM_ + d];
    size_t o = ((size_t)b*LD_ + t)*DM_ + d;
    out[o] = acc;
    bf h = __float2bfloat16(acc);
    H[o] = h; Lo[o] = __float2bfloat16(acc - __bfloat162float(h));
}

// ---------------- pad-row zeroing for padded split buffers ----------------
__global__ void k_padzero(bf* __restrict__ H, bf* __restrict__ L, int Lv){
    int span = LP_ - Lv;
    int n = B_*span*DM_;
    int i = blockIdx.x*256 + threadIdx.x;
    if (i >= n) return;
    int d = i % DM_;
    int rr = (i / DM_) % span;
    int b = i / (DM_*span);
    size_t o = ((size_t)b*LP_ + Lv + rr)*DM_ + d;
    H[o] = __float2bfloat16(0.f);
    L[o] = __float2bfloat16(0.f);
}

// ---------------- mean_corr ----------------
__global__ void k_zero(float* __restrict__ p, int n){
    int i = blockIdx.x*256 + threadIdx.x;
    if (i < n) p[i] = 0.f;
}

__global__ void k_corr2(const float* __restrict__ G, float* __restrict__ corr,
                        int L, int gbs) {
    int b = blockIdx.y, tid = threadIdx.x;
    int t0 = blockIdx.x * 16;
    __shared__ float cs[640];
    for (int i = tid; i < L; i += 256) cs[i] = 0.f;
    __syncthreads();
    const float* Gb = G + (size_t)b*gbs;
    int t1 = min(t0 + 16, L);
    for (int t = t0; t < t1; t++) {
        const float* row = Gb + (size_t)t*L;
        for (int j = tid; j < L; j += 256) {
            int tau = t - j; if (tau < 0) tau += L;
            atomicAdd(&cs[tau], row[j]);
        }
    }
    __syncthreads();
    for (int i = tid; i < L; i += 256)
        atomicAdd(&corr[(size_t)b*L + i], cs[i] * (1.0f/DM_));
}

// ---------------- exact top-k + softmax (warp-shuffle) ----------------
__global__ void k_topk(const float* __restrict__ corr, int L, int KT,
                       int* __restrict__ delay, float* __restrict__ wgt) {
    int b = blockIdx.x, tid = threadIdx.x;
    int lane = tid & 31, wid = tid >> 5;
    __shared__ float vals[640];
    __shared__ float wv[8];
    __shared__ int wi[8];
    __shared__ float tv[32];
    __shared__ int tix[32];
    for (int i = tid; i < L; i += 256) vals[i] = corr[(size_t)b*L + i];
    __syncthreads();
    for (int kt = 0; kt < KT; kt++) {
        float bv = -FLT_MAX; int bi = 0x7fffffff;
        for (int i = tid; i < L; i += 256) {
            float v = vals[i];
            if (v > bv || (v == bv && i < bi)) { bv = v; bi = i; }
        }
        #pragma unroll
        for (int o = 16; o > 0; o >>= 1) {
            float ov = __shfl_down_sync(0xffffffffu, bv, o);
            int   oi = __shfl_down_sync(0xffffffffu, bi, o);
            if (ov > bv || (ov == bv && oi < bi)) { bv = ov; bi = oi; }
        }
        if (lane == 0) { wv[wid] = bv; wi[wid] = bi; }
        __syncthreads();
        if (wid == 0) {
            float v2 = (lane < 8) ? wv[lane] : -FLT_MAX;
            int   i2 = (lane < 8) ? wi[lane] : 0x7fffffff;
            #pragma unroll
            for (int o = 4; o > 0; o >>= 1) {
                float ov = __shfl_down_sync(0xffffffffu, v2, o);
                int   oi = __shfl_down_sync(0xffffffffu, i2, o);
                if (ov > v2 || (ov == v2 && oi < i2)) { v2 = ov; i2 = oi; }
            }
            if (lane == 0) { tv[kt] = v2; tix[kt] = i2; vals[i2] = -FLT_MAX; }
        }
        __syncthreads();
    }
    if (tid == 0) {
        float mx = tv[0], s = 0.f;
        float e[32];
        for (int i = 0; i < KT; i++) { e[i] = expf(tv[i] - mx); s += e[i]; }
        float inv = 1.0f / s;
        for (int i = 0; i < KT; i++) {
            wgt[b*32 + i] = e[i] * inv;
            delay[b*32 + i] = tix[i];
        }
    }
}

// ---------------- weighted circular gather (split out) ----------------
__global__ void k_agg(const float* __restrict__ V, int vld, const int* __restrict__ delay,
                      const float* __restrict__ wgt, bf* __restrict__ OH,
                      bf* __restrict__ OL, int L, int S, int KT, long long vbs) {
    int t = blockIdx.x, b = blockIdx.y, d = threadIdx.x;
    __shared__ int sd[32];
    __shared__ float sw[32];
    if (d < KT) { sd[d] = delay[b*32 + d]; sw[d] = wgt[b*32 + d]; }
    __syncthreads();
    float acc = 0.f;
    for (int i = 0; i < KT; i++) {
        int r = t + sd[i]; if (r >= L) r -= L;
        if (r < S) acc += sw[i] * V[(size_t)b*vbs + (size_t)r*vld + d];
    }
    size_t o = ((size_t)b*L + t)*DM_ + d;
    bf h = __float2bfloat16(acc);
    OH[o] = h; OL[o] = __float2bfloat16(acc - __bfloat162float(h));
}

// ---------------- fused residual add + series_decomp (+ split out) -----------
__global__ void k_add_decomp(const float* __restrict__ X, const float* __restrict__ A,
                             float* __restrict__ S, float* __restrict__ T,
                             bf* __restrict__ SH, bf* __restrict__ SL,
                             int L, int tmode) {
    int b = blockIdx.y, ch = blockIdx.x, d = threadIdx.x;
    int CH = (L + 7) / 8;
    int t0 = ch * CH, t1 = min(t0 + CH, L);
    if (t0 >= L) return;
    const size_t base = (size_t)b * L * DM_ + d;
    float w = 0.f;
    for (int j = -12; j <= 12; j++) {
        int tt = t0 + j; tt = tt < 0 ? 0 : (tt >= L ? L-1 : tt);
        size_t idx = base + (size_t)tt * DM_;
        w += X[idx] + A[idx];
    }
    for (int t = t0; t < t1; t++) {
        size_t idx = base + (size_t)t * DM_;
        float cur = X[idx] + A[idx];
        float m = w * (1.0f/25.0f);
        float sv = cur - m;
        S[idx] = sv;
        bf h = __float2bfloat16(sv);
        SH[idx] = h; SL[idx] = __float2bfloat16(sv - __bfloat162float(h));
        if (tmode == 1) T[idx] = m;
        else if (tmode == 2) T[idx] += m;
        int ta = t + 13; ta = ta >= L ? L-1 : ta;
        int tr = t - 12; tr = tr < 0 ? 0 : tr;
        size_t ia = base + (size_t)ta * DM_;
        size_t ir = base + (size_t)tr * DM_;
        w += (X[ia] + A[ia]) - (X[ir] + A[ir]);
    }
}

// ---------------- layernorm ----------------
__global__ void k_ln(const float* __restrict__ X, const float* __restrict__ g,
                     const float* __restrict__ be, float* __restrict__ Y) {
    int row = blockIdx.x, tid = threadIdx.x;
    __shared__ float buf[DM_];
    __shared__ float red[256];
    __shared__ float smu, sinv;
    const float* xr = X + (size_t)row * DM_;
    float s = 0.f;
    for (int i = tid; i < DM_; i += 256) { float v = xr[i]; buf[i] = v; s += v; }
    red[tid] = s; __syncthreads();
    for (int st = 128; st > 0; st >>= 1) { if (tid < st) red[tid] += red[tid+st]; __syncthreads(); }
    if (tid == 0) smu = red[0] * (1.0f/DM_);
    __syncthreads();
    float mu = smu, s2 = 0.f;
    for (int i = tid; i < DM_; i += 256) { float dv = buf[i] - mu; s2 += dv*dv; }
    red[tid] = s2; __syncthreads();
    for (int st = 128; st > 0; st >>= 1) { if (tid < st) red[tid] += red[tid+st]; __syncthreads(); }
    if (tid == 0) sinv = rsqrtf(red[0] * (1.0f/DM_) + 1e-5f);
    __syncthreads();
    float inv = sinv;
    for (int i = tid; i < DM_; i += 256)
        Y[(size_t)row*DM_ + i] = (buf[i] - mu) * inv * g[i] + be[i];
}

// subtract per-(b,d) time mean; optional split-bf16 emit
__global__ void k_submean2(float* __restrict__ Y, bf* __restrict__ H, bf* __restrict__ L,
                           int Llen) {
    int b = blockIdx.x >> 3, c = blockIdx.x & 7;
    int dl = threadIdx.x & 63, tp = threadIdx.x >> 6;
    int d = c*64 + dl;
    size_t base = (size_t)b*Llen*DM_ + d;
    float s = 0.f;
    for (int t = tp; t < Llen; t += 4) s += Y[base + (size_t)t*DM_];
    __shared__ float red[4][64];
    red[tp][dl] = s; __syncthreads();
    if (tp == 0) red[0][dl] = (red[0][dl]+red[1][dl]+red[2][dl]+red[3][dl]) / (float)Llen;
    __syncthreads();
    float m = red[0][dl];
    for (int t = tp; t < Llen; t += 4) {
        size_t idx = base + (size_t)t*DM_;
        float v = Y[idx] - m;
        Y[idx] = v;
        if (H) {
            bf h = __float2bfloat16(v);
            H[idx] = h; L[idx] = __float2bfloat16(v - __bfloat162float(h));
        }
    }
}

// ---------------- final assembly ----------------
__global__ void k_final(const float* __restrict__ XLN, const float* __restrict__ TS,
                        const float* __restrict__ meanb, const float* __restrict__ Wt,
                        const float* __restrict__ Wp, const float* __restrict__ bp,
                        float* __restrict__ out) {
    int p = blockIdx.x, b = blockIdx.y, tid = threadIdx.x;
    int t = LBL_ + p;
    int r0 = (t - 1 + LD_) % LD_;
    int r2 = (t + 1) % LD_;
    float acc[NC_];
    #pragma unroll
    for (int c = 0; c < NC_; c++) acc[c] = 0.f;
    for (int d = tid; d < DM_; d += 256) {
        float xv  = XLN[((size_t)b*LD_ + t )*DM_ + d];
        float tv0 = TS [((size_t)b*LD_ + r0)*DM_ + d];
        float tv1 = TS [((size_t)b*LD_ + t )*DM_ + d];
        float tv2 = TS [((size_t)b*LD_ + r2)*DM_ + d];
        #pragma unroll
        for (int c = 0; c < NC_; c++) {
            acc[c] += xv  * Wp[(size_t)d*NC_ + c]
                    + tv0 * Wt[((size_t)0*DM_ + d)*NC_ + c]
                    + tv1 * Wt[((size_t)1*DM_ + d)*NC_ + c]
                    + tv2 * Wt[((size_t)2*DM_ + d)*NC_ + c];
        }
    }
    __shared__ float red[256];
    for (int c = 0; c < NC_; c++) {
        red[tid] = acc[c]; __syncthreads();
        for (int st = 128; st > 0; st >>= 1) { if (tid < st) red[tid] += red[tid+st]; __syncthreads(); }
        if (tid == 0)
            out[((size_t)b*PRED_ + p)*NC_ + c] = red[0] + meanb[b*NC_ + c] + bp[c];
        __syncthreads();
    }
}

// ================= host orchestration =================
static bf *ABH, *ABL, *QBH, *QBL, *KBH, *KBL, *HBH, *HBL, *WBH, *WBL;

extern "C" void kernel_launch(void* const* d_in, const int* in_sizes, int n_in,
                              void* d_out, int out_size) {
    const float* x_enc      = (const float*)d_in[0];
    const float* x_mark_enc = (const float*)d_in[1];
    const float* x_mark_dec = (const float*)d_in[3];
    const float* W_enc_emb  = (const float*)d_in[4];
    const float* W_mark_enc = (const float*)d_in[5];
    const float* W_dec_emb  = (const float*)d_in[6];
    const float* W_mark_dec = (const float*)d_in[7];
    const float* eW_attn    = (const float*)d_in[8];
    const float* eb_attn    = (const float*)d_in[9];
    const float* eW1        = (const float*)d_in[10];
    const float* eW2        = (const float*)d_in[11];
    const float* eg         = (const float*)d_in[12];
    const float* ebeta      = (const float*)d_in[13];
    const float* sW         = (const float*)d_in[14];
    const float* sb         = (const float*)d_in[15];
    const float* cW         = (const float*)d_in[16];
    const float* cb         = (const float*)d_in[17];
    const float* dW1        = (const float*)d_in[18];
    const float* dW2        = (const float*)d_in[19];
    const float* W_trend    = (const float*)d_in[20];
    const float* dg         = (const float*)d_in[21];
    const float* dbeta      = (const float*)d_in[22];
    const float* Wproj      = (const float*)d_in[23];
    const float* bproj      = (const float*)d_in[24];
    float* out = (float*)d_out;

    cudaFuncSetAttribute(k_mma, cudaFuncAttributeMaxDynamicSharedMemorySize, SMEM_SZ);

    float* ws = nullptr;
    cudaGetSymbolAddress((void**)&ws, g_ws);
    int* dly = nullptr;
    cudaGetSymbolAddress((void**)&dly, g_delay);
    cudaGetSymbolAddress((void**)&ABH, g_abh);
    cudaGetSymbolAddress((void**)&ABL, g_abl);
    cudaGetSymbolAddress((void**)&QBH, g_qbh);
    cudaGetSymbolAddress((void**)&QBL, g_qbl);
    cudaGetSymbolAddress((void**)&KBH, g_kbh);
    cudaGetSymbolAddress((void**)&KBL, g_kbl);
    cudaGetSymbolAddress((void**)&HBH, g_hbh);
    cudaGetSymbolAddress((void**)&HBL, g_hbl);
    cudaGetSymbolAddress((void**)&WBH, g_wbh);
    cudaGetSymbolAddress((void**)&WBL, g_wbl);

    float* XE   = ws + O_XE;
    float* XA   = ws + O_XA;
    float* XD   = ws + O_XD;
    float* Qb   = ws + O_Q;
    float* Vb   = ws + O_V;
    float* Tb   = ws + O_T;
    float* Gb   = ws + O_G;
    float* CORR = ws + O_CORR;
    float* ENC  = ws + O_ENC;
    float* TS   = ws + O_TS;
    float* SEA  = ws + O_SEA;
    float* MEANB= ws + O_MEAN;
    float* WGT  = ws + O_WGT;

    // ---- fused weight transpose+split (one launch) ----
    k_cvtT_all<<<10240, dim3(32,8)>>>(eW_attn, eW1, eW2, sW, cW, dW1, dW2, WBH, WBL);

    // ---- prep ----
    k_sea<<<(B_*LE_*NC_ + 255)/256, 256>>>(x_enc, SEA);
    k_meanc<<<B_, 256>>>(x_enc, MEANB);
    k_embed_enc<<<dim3(LE_, B_), DM_>>>(x_enc, x_mark_enc, W_enc_emb, W_mark_enc, XE, ABH, ABL);

    // ---- encoder: 2 layers ----
    float* x = XE;
    for (int l = 0; l < 2; l++) {
        const float* bb = eb_attn + (size_t)l*4*DM_;
        size_t wa = OW_EATT + (size_t)l*4*DM_*DM_;
        // merged QKV: Q->QB split, K->KB split (identity layout), V->Vb fp32
        k_mma<<<dim3(12,128,1), 256, SMEM_SZ>>>(ABH, ABL, DM_, WBH+wa, WBL+wa, DM_,
            DM_, B_*LE_, 1536, 0, 0, 0,
            2, Vb, DM_, QBH, QBL, 0, KBH, KBL, LE_, LE_, 4, 4, bb, 0);
        k_mma<<<dim3(4,4,B_), 256, SMEM_SZ>>>(QBH, QBL, DM_, KBH, KBL, DM_,
            DM_, LE_, LE_, (long long)LE_*DM_, (long long)LE_*DM_, (long long)LE_*LE_,
            0, Gb, LE_, nullptr, nullptr, 0, nullptr, nullptr, LE_, LE_, 0, 0, nullptr, 0);
        k_zero<<<(B_*LE_ + 255)/256, 256>>>(CORR, B_*LE_);
        k_corr2<<<dim3(LE_/16, B_), 256>>>(Gb, CORR, LE_, LE_*LE_);
        k_topk<<<B_, 256>>>(CORR, LE_, KT_E, dly, WGT);
        k_agg<<<dim3(LE_, B_), DM_>>>(Vb, DM_, dly, WGT, ABH, ABL,
                                      LE_, LE_, KT_E, (long long)LE_*DM_);
        k_mma<<<dim3(4,128,1), 256, SMEM_SZ>>>(ABH, ABL, DM_,
            WBH+wa+3*(size_t)DM_*DM_, WBL+wa+3*(size_t)DM_*DM_, DM_,
            DM_, B_*LE_, DM_, 0, 0, 0,
            0, Tb, DM_, nullptr, nullptr, 0, nullptr, nullptr, LE_, LE_, 0, 0, bb+3*DM_, 0);
        float* nx = (x == XE) ? XA : XE;
        k_add_decomp<<<dim3(8, B_), DM_>>>(x, Tb, nx, nullptr, ABH, ABL, LE_, 0);
        x = nx;
        k_mma<<<dim3(16,128,1), 256, SMEM_SZ>>>(ABH, ABL, DM_,
            WBH+OW_EW1+(size_t)l*DM_*DFF_, WBL+OW_EW1+(size_t)l*DM_*DFF_, DM_,
            DM_, B_*LE_, DFF_, 0, 0, 0,
            1, nullptr, 0, HBH, HBL, DFF_, nullptr, nullptr, LE_, LE_, 0, 0, nullptr, 1);
        k_mma<<<dim3(4,128,1), 256, SMEM_SZ>>>(HBH, HBL, DFF_,
            WBH+OW_EW2+(size_t)l*DFF_*DM_, WBL+OW_EW2+(size_t)l*DFF_*DM_, DFF_,
            DFF_, B_*LE_, DM_, 0, 0, 0,
            0, Tb, DM_, nullptr, nullptr, 0, nullptr, nullptr, LE_, LE_, 0, 0, nullptr, 0);
        nx = (x == XE) ? XA : XE;
        k_add_decomp<<<dim3(8, B_), DM_>>>(x, Tb, nx, nullptr, ABH, ABL, LE_, 0);
        x = nx;
    }
    k_ln<<<B_*LE_, 256>>>(x, eg, ebeta, ENC);
    k_submean2<<<B_*8, 256>>>(ENC, HBH, HBL, LE_);   // ENC split cached in HBH/HBL

    // ---- decoder ----
    k_embed_dec<<<dim3(LD_, B_), DM_>>>(SEA, x_mark_enc, x_mark_dec, W_dec_emb, W_mark_dec, XD, ABH, ABL);
    float* xd = XD;

    // zero pad rows [592,640) of QB/KB (dirtied by encoder's dense usage)
    {
        int n = B_*(LP_-LD_)*DM_;
        k_padzero<<<(n+255)/256, 256>>>(QBH, QBL, LD_);
        k_padzero<<<(n+255)/256, 256>>>(KBH, KBL, LD_);
    }

    // self attention (merged QKV; Q/K padded split, V fp32 dense)
    k_mma<<<dim3(12,148,1), 256, SMEM_SZ>>>(ABH, ABL, DM_, WBH+OW_SW, WBL+OW_SW, DM_,
        DM_, B_*LD_, 1536, 0, 0, 0,
        2, Vb, DM_, QBH, QBL, 0, KBH, KBL, LD_, LP_, 4, 4, sb, 0);
    k_mma<<<dim3(5,5,B_), 256, SMEM_SZ>>>(QBH, QBL, DM_, KBH, KBL, DM_,
        DM_, LD_, LD_, (long long)LP_*DM_, (long long)LP_*DM_, (long long)LD_*LD_,
        0, Gb, LD_, nullptr, nullptr, 0, nullptr, nullptr, LD_, LD_, 0, 0, nullptr, 0);
    k_zero<<<(B_*LD_ + 255)/256, 256>>>(CORR, B_*LD_);
    k_corr2<<<dim3((LD_+15)/16, B_), 256>>>(Gb, CORR, LD_, LD_*LD_);
    k_topk<<<B_, 256>>>(CORR, LD_, KT_D, dly, WGT);
    k_agg<<<dim3(LD_, B_), DM_>>>(Vb, DM_, dly, WGT, ABH, ABL,
                                  LD_, LD_, KT_D, (long long)LD_*DM_);
    k_mma<<<dim3(4,148,1), 256, SMEM_SZ>>>(ABH, ABL, DM_,
        WBH+OW_SW+3*(size_t)DM_*DM_, WBL+OW_SW+3*(size_t)DM_*DM_, DM_,
        DM_, B_*LD_, DM_, 0, 0, 0,
        0, Tb, DM_, nullptr, nullptr, 0, nullptr, nullptr, LD_, LD_, 0, 0, sb+3*DM_, 0);
    k_add_decomp<<<dim3(8, B_), DM_>>>(xd, Tb, XA, TS, ABH, ABL, LD_, 1);
    xd = XA;

    // cross attention: Q from x (padded split), K/V merged from ENC split
    k_mma<<<dim3(4,148,1), 256, SMEM_SZ>>>(ABH, ABL, DM_, WBH+OW_CW, WBL+OW_CW, DM_,
        DM_, B_*LD_, DM_, 0, 0, 0,
        1, nullptr, 0, QBH, QBL, DM_, nullptr, nullptr, LD_, LP_, 0, 0, cb, 0);
    {
        int n = B_*(LP_-LE_)*DM_;
        k_padzero<<<(n+255)/256, 256>>>(KBH, KBL, LE_);
    }
    k_mma<<<dim3(8,128,1), 256, SMEM_SZ>>>(HBH, HBL, DM_,
        WBH+OW_CW+(size_t)DM_*DM_, WBL+OW_CW+(size_t)DM_*DM_, DM_,
        DM_, B_*LE_, 1024, 0, 0, 0,
        3, Vb, DM_, nullptr, nullptr, 0, KBH, KBL, LE_, LP_, 0, 4, cb+DM_, 0);
    k_mma<<<dim3(5,5,B_), 256, SMEM_SZ>>>(QBH, QBL, DM_, KBH, KBL, DM_,
        DM_, LD_, LD_, (long long)LP_*DM_, (long long)LP_*DM_, (long long)LD_*LD_,
        0, Gb, LD_, nullptr, nullptr, 0, nullptr, nullptr, LD_, LD_, 0, 0, nullptr, 0);
    k_zero<<<(B_*LD_ + 255)/256, 256>>>(CORR, B_*LD_);
    k_corr2<<<dim3((LD_+15)/16, B_), 256>>>(Gb, CORR, LD_, LD_*LD_);
    k_topk<<<B_, 256>>>(CORR, LD_, KT_D, dly, WGT);
    k_agg<<<dim3(LD_, B_), DM_>>>(Vb, DM_, dly, WGT, ABH, ABL,
                                  LD_, LE_, KT_D, (long long)LE_*DM_);
    k_mma<<<dim3(4,148,1), 256, SMEM_SZ>>>(ABH, ABL, DM_,
        WBH+OW_CW+3*(size_t)DM_*DM_, WBL+OW_CW+3*(size_t)DM_*DM_, DM_,
        DM_, B_*LD_, DM_, 0, 0, 0,
        0, Tb, DM_, nullptr, nullptr, 0, nullptr, nullptr, LD_, LD_, 0, 0, cb+3*DM_, 0);
    k_add_decomp<<<dim3(8, B_), DM_>>>(xd, Tb, XD, TS, ABH, ABL, LD_, 2);
    xd = XD;

    // FFN (HBH/HBL free now — ENC split consumed by cross-KV GEMM above)
    k_mma<<<dim3(16,148,1), 256, SMEM_SZ>>>(ABH, ABL, DM_,
        WBH+OW_DW1, WBL+OW_DW1, DM_,
        DM_, B_*LD_, DFF_, 0, 0, 0,
        1, nullptr, 0, HBH, HBL, DFF_, nullptr, nullptr, LD_, LD_, 0, 0, nullptr, 1);
    k_mma<<<dim3(4,148,1), 256, SMEM_SZ>>>(HBH, HBL, DFF_,
        WBH+OW_DW2, WBL+OW_DW2, DFF_,
        DFF_, B_*LD_, DM_, 0, 0, 0,
        0, Tb, DM_, nullptr, nullptr, 0, nullptr, nullptr, LD_, LD_, 0, 0, nullptr, 0);
    k_add_decomp<<<dim3(8, B_), DM_>>>(xd, Tb, XA, TS, ABH, ABL, LD_, 2);
    xd = XA;

    // final layernorm + output assembly
    k_ln<<<B_*LD_, 256>>>(xd, dg, dbeta, Qb);
    k_submean2<<<B_*8, 256>>>(Qb, nullptr, nullptr, LD_);
    k_final<<<dim3(PRED_, B_), 256>>>(Qb, TS, MEANB, W_trend, Wproj, bproj, out);
}